// round 2
// baseline (speedup 1.0000x reference)
#include <cuda_runtime.h>
#include <math.h>

#define L    512
#define T    96
#define CIN  150
#define HID  150
#define J3   450
#define J3P  480   // padded xi column stride
#define KW   5
#define KTOT 750   // KW*CIN

// ---------------- scratch ----------------
__device__ float g_xi [(size_t)T * L * J3P];   // (t, l, 480)
__device__ float g_ys0[(size_t)L * T * HID];   // layer-0 output (l, t, h)
__device__ float g_h  [2 * L * HID];           // ping-pong hidden state
__device__ unsigned g_cnt;
__device__ volatile unsigned g_gen;

// ---------------- f32x2 helpers ----------------
__device__ __forceinline__ unsigned long long pk2(float lo, float hi) {
    unsigned long long r;
    asm("mov.b64 %0, {%1, %2};" : "=l"(r)
        : "r"(__float_as_uint(lo)), "r"(__float_as_uint(hi)));
    return r;
}
__device__ __forceinline__ void ffma2(unsigned long long& d,
                                      unsigned long long a,
                                      unsigned long long b) {
    asm("fma.rn.f32x2 %0, %1, %2, %0;" : "+l"(d) : "l"(a), "l"(b));
}
__device__ __forceinline__ float2 upk2(unsigned long long v) {
    unsigned lo, hi;
    asm("mov.b64 {%0, %1}, %2;" : "=r"(lo), "=r"(hi) : "l"(v));
    return make_float2(__uint_as_float(lo), __uint_as_float(hi));
}
__device__ __forceinline__ float sigf(float x) {
    float e = __expf(-x);
    return __fdividef(1.f, 1.f + e);
}
__device__ __forceinline__ float tanhfast(float x) {
    return 2.f * sigf(2.f * x) - 1.f;
}

// =====================================================================
// xi kernel: xi[t][l][j] = b[j] + sum_{tap,c} x[l+tap-2][t][c]*Wi[tap][c][j]
// grid (10, 8, 96), 256 threads, microtile 2 rows x 6 cols (3 f32x2 pairs)
// =====================================================================
#define XBL 64
#define XBJ 48
extern __shared__ float smem[];

__global__ __launch_bounds__(256) void xi_kernel(
    const float* __restrict__ x, const float* __restrict__ Wi,
    const float* __restrict__ bi, float* __restrict__ xi)
{
    float* sh_x = smem;                      // (XBL+4) x 150
    float* sh_w = smem + (XBL + 4) * CIN;    // 150 x 48

    const int t  = blockIdx.z;
    const int l0 = blockIdx.y * XBL;
    const int j0 = blockIdx.x * XBJ;
    const int tid = threadIdx.x;
    const int tx = tid & 7;          // 0..7, 6 cols each
    const int ty = tid >> 3;         // 0..31, 2 rows each
    const int tx6 = tx * 6;
    const int r0 = ty * 2;

    for (int idx = tid; idx < (XBL + 4) * CIN; idx += 256) {
        int r = idx / CIN, c = idx - r * CIN;
        int l = l0 - 2 + r;
        sh_x[idx] = (l >= 0 && l < L) ? x[((size_t)l * T + t) * CIN + c] : 0.f;
    }

    unsigned long long acc[2][3];
    #pragma unroll
    for (int i = 0; i < 2; i++)
        #pragma unroll
        for (int k = 0; k < 3; k++) acc[i][k] = 0ull;

    for (int tap = 0; tap < KW; tap++) {
        __syncthreads();
        for (int idx = tid; idx < CIN * XBJ; idx += 256) {
            int c = idx / XBJ, j = idx - c * XBJ;
            int jg = j0 + j;
            sh_w[idx] = (jg < J3) ? Wi[((size_t)tap * CIN + c) * J3 + jg] : 0.f;
        }
        __syncthreads();

        const float* xa = sh_x + (r0 + tap) * CIN;
        const float* wb = sh_w + tx6;
        #pragma unroll 2
        for (int c = 0; c < CIN; c++) {
            float a0 = xa[c];
            float a1 = xa[CIN + c];
            unsigned long long A0 = pk2(a0, a0);
            unsigned long long A1 = pk2(a1, a1);
            const float* wr = wb + c * XBJ;
            unsigned long long b0 = *reinterpret_cast<const unsigned long long*>(wr);
            unsigned long long b1 = *reinterpret_cast<const unsigned long long*>(wr + 2);
            unsigned long long b2 = *reinterpret_cast<const unsigned long long*>(wr + 4);
            ffma2(acc[0][0], A0, b0); ffma2(acc[0][1], A0, b1); ffma2(acc[0][2], A0, b2);
            ffma2(acc[1][0], A1, b0); ffma2(acc[1][1], A1, b1); ffma2(acc[1][2], A1, b2);
        }
    }

    float bb[6];
    #pragma unroll
    for (int k = 0; k < 6; k++) {
        int jg = j0 + tx6 + k;
        bb[k] = (jg < J3) ? bi[jg] : 0.f;
    }
    #pragma unroll
    for (int i = 0; i < 2; i++) {
        float* dst = xi + ((size_t)t * L + l0 + r0 + i) * J3P + j0 + tx6;
        #pragma unroll
        for (int k = 0; k < 3; k++) {
            float2 v = upk2(acc[i][k]);
            dst[2 * k]     = v.x + bb[2 * k];
            dst[2 * k + 1] = v.y + bb[2 * k + 1];
        }
    }
}

// =====================================================================
// Persistent recurrent kernel: 96 GRU steps, weights resident in smem.
// grid (10 channel-groups, 14 l-groups) = 140 blocks (1/SM), 160 threads.
// Block owns 15 channels x all 3 gates (45 cols, padded 48) x <=37 rows.
// =====================================================================
#define CG    10
#define CHG   15     // channels per group
#define NCOL  45
#define NCOLP 48
#define LG    14
#define BLMAX 37
#define NBLK  (CG * LG)
#define RTHR  160

__device__ __forceinline__ void grid_barrier(unsigned target) {
    __threadfence();
    __syncthreads();
    if (threadIdx.x == 0) {
        unsigned a = atomicAdd(&g_cnt, 1u);
        if (a == NBLK - 1u) {
            g_cnt = 0u;
            __threadfence();
            g_gen = target;
        } else {
            while (g_gen < target) { }
            __threadfence();
        }
    }
    __syncthreads();
}

__global__ void init_barrier() { g_cnt = 0u; g_gen = 0u; }

__global__ __launch_bounds__(RTHR, 1) void rec_kernel(
    const float* __restrict__ Wh,
    const float* __restrict__ xi,
    float* __restrict__ ys)
{
    float* sh_w  = smem;                        // [750][48]
    float* sh_h  = sh_w + KTOT * NCOLP;         // [41][150]
    float* sh_hh = sh_h + (BLMAX + 4) * HID;    // [37][48]

    const int cg = blockIdx.x, lg = blockIdx.y;
    const int c0 = cg * CHG;
    const int l0 = lg * BLMAX;
    const int BL = min(BLMAX, L - l0);
    const int tid = threadIdx.x;
    const int tx = tid & 7;         // 6 cols each
    const int ty = tid >> 3;        // 0..19, 2 rows each
    const int tx6 = tx * 6;
    const int r0 = ty * 2;

    // load weight slice once (columns: gate*15 blocks of channels)
    for (int idx = tid; idx < KTOT * NCOL; idx += RTHR) {
        int k = idx / NCOL, jj = idx - k * NCOL;
        int gate = jj / CHG, ch = jj - gate * CHG;
        sh_w[k * NCOLP + jj] = Wh[(size_t)k * J3 + gate * HID + c0 + ch];
    }
    for (int idx = tid; idx < KTOT; idx += RTHR) {
        sh_w[idx * NCOLP + 45] = 0.f;
        sh_w[idx * NCOLP + 46] = 0.f;
        sh_w[idx * NCOLP + 47] = 0.f;
    }

    float* hA = g_h;
    float* hB = g_h + L * HID;
    // zero initial hidden state (this block's slice)
    for (int e = tid; e < BL * CHG; e += RTHR) {
        int lr = e / CHG, ch = e - lr * CHG;
        hA[(l0 + lr) * HID + c0 + ch] = 0.f;
    }
    unsigned bar = 1;
    grid_barrier(bar++);

    const bool v0 = (r0 < BL), v1 = (r0 + 1 < BL);
    const int ra0 = v0 ? r0 : 0;
    const int ra1 = v1 ? r0 + 1 : 0;

    for (int t = 0; t < T; t++) {
        // stage h rows [l0-2, l0+BL+2)
        for (int idx = tid; idx < (BL + 4) * HID; idx += RTHR) {
            int r = idx / HID, c = idx - r * HID;
            int l = l0 - 2 + r;
            sh_h[idx] = (l >= 0 && l < L) ? hA[l * HID + c] : 0.f;
        }
        __syncthreads();

        unsigned long long acc[2][3];
        #pragma unroll
        for (int i = 0; i < 2; i++)
            #pragma unroll
            for (int k = 0; k < 3; k++) acc[i][k] = 0ull;

        for (int tap = 0; tap < KW; tap++) {
            const float* ha0 = sh_h + (ra0 + tap) * HID;
            const float* ha1 = sh_h + (ra1 + tap) * HID;
            const float* wb  = sh_w + tap * CIN * NCOLP + tx6;
            #pragma unroll 2
            for (int c = 0; c < CIN; c++) {
                float a0 = ha0[c];
                float a1 = ha1[c];
                unsigned long long A0 = pk2(a0, a0);
                unsigned long long A1 = pk2(a1, a1);
                const float* wr = wb + c * NCOLP;
                unsigned long long b0 = *reinterpret_cast<const unsigned long long*>(wr);
                unsigned long long b1 = *reinterpret_cast<const unsigned long long*>(wr + 2);
                unsigned long long b2 = *reinterpret_cast<const unsigned long long*>(wr + 4);
                ffma2(acc[0][0], A0, b0); ffma2(acc[0][1], A0, b1); ffma2(acc[0][2], A0, b2);
                ffma2(acc[1][0], A1, b0); ffma2(acc[1][1], A1, b1); ffma2(acc[1][2], A1, b2);
            }
        }

        // stage hh into smem for gate regrouping
        if (v0) {
            float2* d = reinterpret_cast<float2*>(sh_hh + r0 * NCOLP + tx6);
            d[0] = upk2(acc[0][0]); d[1] = upk2(acc[0][1]); d[2] = upk2(acc[0][2]);
        }
        if (v1) {
            float2* d = reinterpret_cast<float2*>(sh_hh + (r0 + 1) * NCOLP + tx6);
            d[0] = upk2(acc[1][0]); d[1] = upk2(acc[1][1]); d[2] = upk2(acc[1][2]);
        }
        __syncthreads();

        // gate epilogue
        const float* xit = xi + ((size_t)t * L + l0) * J3P;
        for (int e = tid; e < BL * CHG; e += RTHR) {
            int lr = e / CHG, ch = e - lr * CHG;
            float hr = sh_hh[lr * NCOLP + ch];
            float hz = sh_hh[lr * NCOLP + CHG + ch];
            float hn = sh_hh[lr * NCOLP + 2 * CHG + ch];
            float hp = sh_h[(lr + 2) * HID + c0 + ch];
            const float* q = xit + (size_t)lr * J3P;
            float xr = q[c0 + ch];
            float xz = q[HID + c0 + ch];
            float xn = q[2 * HID + c0 + ch];
            float r = sigf(xr + hr);
            float z = sigf(xz + hz);
            float n = tanhfast(xn + r * hn);
            float hnew = n + z * (hp - n);
            hB[(l0 + lr) * HID + c0 + ch] = hnew;
            ys[((size_t)(l0 + lr) * T + t) * HID + c0 + ch] = hnew;
        }

        grid_barrier(bar++);
        float* tmp = hA; hA = hB; hB = tmp;
    }
}

// =====================================================================
extern "C" void kernel_launch(void* const* d_in, const int* in_sizes, int n_in,
                              void* d_out, int out_size)
{
    (void)in_sizes; (void)n_in; (void)out_size;
    const float* xs  = (const float*)d_in[0];
    const float* Wi0 = (const float*)d_in[1];
    const float* bi0 = (const float*)d_in[2];
    const float* Wh0 = (const float*)d_in[3];
    const float* Wi1 = (const float*)d_in[4];
    const float* bi1 = (const float*)d_in[5];
    const float* Wh1 = (const float*)d_in[6];
    float* out = (float*)d_out;

    float *xi, *ys0;
    cudaGetSymbolAddress((void**)&xi,  g_xi);
    cudaGetSymbolAddress((void**)&ys0, g_ys0);

    const size_t smem_xi  = ((XBL + 4) * CIN + CIN * XBJ) * sizeof(float);          // 69.6 KB
    const size_t smem_rec = (KTOT * NCOLP + (BLMAX + 4) * HID + BLMAX * NCOLP) * sizeof(float); // 175.7 KB
    static int attr_done = 0;
    if (!attr_done) {
        cudaFuncSetAttribute(xi_kernel,  cudaFuncAttributeMaxDynamicSharedMemorySize, (int)smem_xi);
        cudaFuncSetAttribute(rec_kernel, cudaFuncAttributeMaxDynamicSharedMemorySize, (int)smem_rec);
        attr_done = 1;
    }

    const dim3 grid_xi(J3P / XBJ, L / XBL, T);   // (10, 8, 96)
    const dim3 grid_rec(CG, LG);                 // (10, 14) = 140 blocks

    for (int layer = 0; layer < 2; layer++) {
        const float* x  = layer ? (const float*)ys0 : xs;
        const float* Wi = layer ? Wi1 : Wi0;
        const float* bi = layer ? bi1 : bi0;
        const float* Wh = layer ? Wh1 : Wh0;
        float*       ys = layer ? out : ys0;

        xi_kernel<<<grid_xi, 256, smem_xi>>>(x, Wi, bi, xi);
        init_barrier<<<1, 1>>>();
        rec_kernel<<<grid_rec, RTHR, smem_rec>>>(Wh, xi, ys);
    }
}

// round 3
// speedup vs baseline: 1.0034x; 1.0034x over previous
#include <cuda_runtime.h>
#include <math.h>

#define L    512
#define T    96
#define CIN  150
#define HID  150
#define J3   450
#define J3P  480   // padded xi column stride
#define KW   5
#define KTOT 750   // KW*CIN

// ---------------- scratch ----------------
__device__ float g_xi [(size_t)T * L * J3P];   // (t, l, 480)
__device__ float g_ys0[(size_t)L * T * HID];   // layer-0 output (l, t, h)
__device__ float g_h  [2 * L * HID];           // ping-pong hidden state
__device__ unsigned g_cnt;
__device__ volatile unsigned g_gen;

// ---------------- f32x2 helpers ----------------
__device__ __forceinline__ unsigned long long pk2(float lo, float hi) {
    unsigned long long r;
    asm("mov.b64 %0, {%1, %2};" : "=l"(r)
        : "r"(__float_as_uint(lo)), "r"(__float_as_uint(hi)));
    return r;
}
__device__ __forceinline__ void ffma2(unsigned long long& d,
                                      unsigned long long a,
                                      unsigned long long b) {
    asm("fma.rn.f32x2 %0, %1, %2, %0;" : "+l"(d) : "l"(a), "l"(b));
}
__device__ __forceinline__ float2 upk2(unsigned long long v) {
    unsigned lo, hi;
    asm("mov.b64 {%0, %1}, %2;" : "=r"(lo), "=r"(hi) : "l"(v));
    return make_float2(__uint_as_float(lo), __uint_as_float(hi));
}
__device__ __forceinline__ float sigf(float x) {
    float e = __expf(-x);
    return __fdividef(1.f, 1.f + e);
}
__device__ __forceinline__ float tanhfast(float x) {
    return 2.f * sigf(2.f * x) - 1.f;
}

// =====================================================================
// xi kernel: xi[t][l][j] = b[j] + sum_{tap,c} x[l+tap-2][t][c]*Wi[tap][c][j]
// grid (10, 8, 96), 256 threads, microtile 2 rows x 6 cols (3 f32x2 pairs)
// =====================================================================
#define XBL 64
#define XBJ 48
extern __shared__ float smem[];

__global__ __launch_bounds__(256) void xi_kernel(
    const float* __restrict__ x, const float* __restrict__ Wi,
    const float* __restrict__ bi, float* __restrict__ xi)
{
    float* sh_x = smem;                      // (XBL+4) x 150
    float* sh_w = smem + (XBL + 4) * CIN;    // 150 x 48

    const int t  = blockIdx.z;
    const int l0 = blockIdx.y * XBL;
    const int j0 = blockIdx.x * XBJ;
    const int tid = threadIdx.x;
    const int tx = tid & 7;          // 0..7, 6 cols each
    const int ty = tid >> 3;         // 0..31, 2 rows each
    const int tx6 = tx * 6;
    const int r0 = ty * 2;

    for (int idx = tid; idx < (XBL + 4) * CIN; idx += 256) {
        int r = idx / CIN, c = idx - r * CIN;
        int l = l0 - 2 + r;
        sh_x[idx] = (l >= 0 && l < L) ? x[((size_t)l * T + t) * CIN + c] : 0.f;
    }

    unsigned long long acc[2][3];
    #pragma unroll
    for (int i = 0; i < 2; i++)
        #pragma unroll
        for (int k = 0; k < 3; k++) acc[i][k] = 0ull;

    for (int tap = 0; tap < KW; tap++) {
        __syncthreads();
        for (int idx = tid; idx < CIN * XBJ; idx += 256) {
            int c = idx / XBJ, j = idx - c * XBJ;
            int jg = j0 + j;
            sh_w[idx] = (jg < J3) ? Wi[((size_t)tap * CIN + c) * J3 + jg] : 0.f;
        }
        __syncthreads();

        const float* xa = sh_x + (r0 + tap) * CIN;
        const float* wb = sh_w + tx6;
        #pragma unroll 2
        for (int c = 0; c < CIN; c++) {
            float a0 = xa[c];
            float a1 = xa[CIN + c];
            unsigned long long A0 = pk2(a0, a0);
            unsigned long long A1 = pk2(a1, a1);
            const float* wr = wb + c * XBJ;
            unsigned long long b0 = *reinterpret_cast<const unsigned long long*>(wr);
            unsigned long long b1 = *reinterpret_cast<const unsigned long long*>(wr + 2);
            unsigned long long b2 = *reinterpret_cast<const unsigned long long*>(wr + 4);
            ffma2(acc[0][0], A0, b0); ffma2(acc[0][1], A0, b1); ffma2(acc[0][2], A0, b2);
            ffma2(acc[1][0], A1, b0); ffma2(acc[1][1], A1, b1); ffma2(acc[1][2], A1, b2);
        }
    }

    float bb[6];
    #pragma unroll
    for (int k = 0; k < 6; k++) {
        int jg = j0 + tx6 + k;
        bb[k] = (jg < J3) ? bi[jg] : 0.f;
    }
    #pragma unroll
    for (int i = 0; i < 2; i++) {
        float* dst = xi + ((size_t)t * L + l0 + r0 + i) * J3P + j0 + tx6;
        #pragma unroll
        for (int k = 0; k < 3; k++) {
            float2 v = upk2(acc[i][k]);
            dst[2 * k]     = v.x + bb[2 * k];
            dst[2 * k + 1] = v.y + bb[2 * k + 1];
        }
    }
}

// =====================================================================
// Persistent recurrent kernel: 96 GRU steps, weights resident in smem.
// grid (10 channel-groups, 14 l-groups) = 140 blocks (1/SM), 160 threads.
// Block owns 15 channels x all 3 gates (45 cols, padded 48) x <=37 rows.
// =====================================================================
#define CG    10
#define CHG   15     // channels per group
#define NCOL  45
#define NCOLP 48
#define LG    14
#define BLMAX 37
#define NBLK  (CG * LG)
#define RTHR  160

__device__ __forceinline__ void grid_barrier(unsigned target) {
    __threadfence();
    __syncthreads();
    if (threadIdx.x == 0) {
        unsigned a = atomicAdd(&g_cnt, 1u);
        if (a == NBLK - 1u) {
            g_cnt = 0u;
            __threadfence();
            g_gen = target;
        } else {
            while (g_gen < target) { }
            __threadfence();
        }
    }
    __syncthreads();
}

__global__ void init_barrier() { g_cnt = 0u; g_gen = 0u; }

__global__ __launch_bounds__(RTHR, 1) void rec_kernel(
    const float* __restrict__ Wh,
    const float* __restrict__ xi,
    float* __restrict__ ys)
{
    float* sh_w  = smem;                        // [750][48]
    float* sh_h  = sh_w + KTOT * NCOLP;         // [41][150]
    float* sh_hh = sh_h + (BLMAX + 4) * HID;    // [37][48]

    const int cg = blockIdx.x, lg = blockIdx.y;
    const int c0 = cg * CHG;
    const int l0 = lg * BLMAX;
    const int BL = min(BLMAX, L - l0);
    const int tid = threadIdx.x;
    const int tx = tid & 7;         // 6 cols each
    const int ty = tid >> 3;        // 0..19, 2 rows each
    const int tx6 = tx * 6;
    const int r0 = ty * 2;

    // load weight slice once (columns: gate*15 blocks of channels)
    for (int idx = tid; idx < KTOT * NCOL; idx += RTHR) {
        int k = idx / NCOL, jj = idx - k * NCOL;
        int gate = jj / CHG, ch = jj - gate * CHG;
        sh_w[k * NCOLP + jj] = Wh[(size_t)k * J3 + gate * HID + c0 + ch];
    }
    for (int idx = tid; idx < KTOT; idx += RTHR) {
        sh_w[idx * NCOLP + 45] = 0.f;
        sh_w[idx * NCOLP + 46] = 0.f;
        sh_w[idx * NCOLP + 47] = 0.f;
    }

    float* hA = g_h;
    float* hB = g_h + L * HID;
    // zero initial hidden state (this block's slice)
    for (int e = tid; e < BL * CHG; e += RTHR) {
        int lr = e / CHG, ch = e - lr * CHG;
        hA[(l0 + lr) * HID + c0 + ch] = 0.f;
    }
    unsigned bar = 1;
    grid_barrier(bar++);

    const bool v0 = (r0 < BL), v1 = (r0 + 1 < BL);
    const int ra0 = v0 ? r0 : 0;
    const int ra1 = v1 ? r0 + 1 : 0;

    for (int t = 0; t < T; t++) {
        // stage h rows [l0-2, l0+BL+2)
        for (int idx = tid; idx < (BL + 4) * HID; idx += RTHR) {
            int r = idx / HID, c = idx - r * HID;
            int l = l0 - 2 + r;
            sh_h[idx] = (l >= 0 && l < L) ? hA[l * HID + c] : 0.f;
        }
        __syncthreads();

        unsigned long long acc[2][3];
        #pragma unroll
        for (int i = 0; i < 2; i++)
            #pragma unroll
            for (int k = 0; k < 3; k++) acc[i][k] = 0ull;

        for (int tap = 0; tap < KW; tap++) {
            const float* ha0 = sh_h + (ra0 + tap) * HID;
            const float* ha1 = sh_h + (ra1 + tap) * HID;
            const float* wb  = sh_w + tap * CIN * NCOLP + tx6;
            #pragma unroll 2
            for (int c = 0; c < CIN; c++) {
                float a0 = ha0[c];
                float a1 = ha1[c];
                unsigned long long A0 = pk2(a0, a0);
                unsigned long long A1 = pk2(a1, a1);
                const float* wr = wb + c * NCOLP;
                unsigned long long b0 = *reinterpret_cast<const unsigned long long*>(wr);
                unsigned long long b1 = *reinterpret_cast<const unsigned long long*>(wr + 2);
                unsigned long long b2 = *reinterpret_cast<const unsigned long long*>(wr + 4);
                ffma2(acc[0][0], A0, b0); ffma2(acc[0][1], A0, b1); ffma2(acc[0][2], A0, b2);
                ffma2(acc[1][0], A1, b0); ffma2(acc[1][1], A1, b1); ffma2(acc[1][2], A1, b2);
            }
        }

        // stage hh into smem for gate regrouping
        if (v0) {
            float2* d = reinterpret_cast<float2*>(sh_hh + r0 * NCOLP + tx6);
            d[0] = upk2(acc[0][0]); d[1] = upk2(acc[0][1]); d[2] = upk2(acc[0][2]);
        }
        if (v1) {
            float2* d = reinterpret_cast<float2*>(sh_hh + (r0 + 1) * NCOLP + tx6);
            d[0] = upk2(acc[1][0]); d[1] = upk2(acc[1][1]); d[2] = upk2(acc[1][2]);
        }
        __syncthreads();

        // gate epilogue
        const float* xit = xi + ((size_t)t * L + l0) * J3P;
        for (int e = tid; e < BL * CHG; e += RTHR) {
            int lr = e / CHG, ch = e - lr * CHG;
            float hr = sh_hh[lr * NCOLP + ch];
            float hz = sh_hh[lr * NCOLP + CHG + ch];
            float hn = sh_hh[lr * NCOLP + 2 * CHG + ch];
            float hp = sh_h[(lr + 2) * HID + c0 + ch];
            const float* q = xit + (size_t)lr * J3P;
            float xr = q[c0 + ch];
            float xz = q[HID + c0 + ch];
            float xn = q[2 * HID + c0 + ch];
            float r = sigf(xr + hr);
            float z = sigf(xz + hz);
            float n = tanhfast(xn + r * hn);
            float hnew = n + z * (hp - n);
            hB[(l0 + lr) * HID + c0 + ch] = hnew;
            ys[((size_t)(l0 + lr) * T + t) * HID + c0 + ch] = hnew;
        }

        grid_barrier(bar++);
        float* tmp = hA; hA = hB; hB = tmp;
    }
}

// =====================================================================
extern "C" void kernel_launch(void* const* d_in, const int* in_sizes, int n_in,
                              void* d_out, int out_size)
{
    (void)in_sizes; (void)n_in; (void)out_size;
    const float* xs  = (const float*)d_in[0];
    const float* Wi0 = (const float*)d_in[1];
    const float* bi0 = (const float*)d_in[2];
    const float* Wh0 = (const float*)d_in[3];
    const float* Wi1 = (const float*)d_in[4];
    const float* bi1 = (const float*)d_in[5];
    const float* Wh1 = (const float*)d_in[6];
    float* out = (float*)d_out;

    float *xi, *ys0;
    cudaGetSymbolAddress((void**)&xi,  g_xi);
    cudaGetSymbolAddress((void**)&ys0, g_ys0);

    const size_t smem_xi  = ((XBL + 4) * CIN + CIN * XBJ) * sizeof(float);          // 69.6 KB
    const size_t smem_rec = (KTOT * NCOLP + (BLMAX + 4) * HID + BLMAX * NCOLP) * sizeof(float); // 175.7 KB
    static int attr_done = 0;
    if (!attr_done) {
        cudaFuncSetAttribute(xi_kernel,  cudaFuncAttributeMaxDynamicSharedMemorySize, (int)smem_xi);
        cudaFuncSetAttribute(rec_kernel, cudaFuncAttributeMaxDynamicSharedMemorySize, (int)smem_rec);
        attr_done = 1;
    }

    const dim3 grid_xi(J3P / XBJ, L / XBL, T);   // (10, 8, 96)
    const dim3 grid_rec(CG, LG);                 // (10, 14) = 140 blocks

    for (int layer = 0; layer < 2; layer++) {
        const float* x  = layer ? (const float*)ys0 : xs;
        const float* Wi = layer ? Wi1 : Wi0;
        const float* bi = layer ? bi1 : bi0;
        const float* Wh = layer ? Wh1 : Wh0;
        float*       ys = layer ? out : ys0;

        xi_kernel<<<grid_xi, 256, smem_xi>>>(x, Wi, bi, xi);
        init_barrier<<<1, 1>>>();
        rec_kernel<<<grid_rec, RTHR, smem_rec>>>(Wh, xi, ys);
    }
}

// round 5
// speedup vs baseline: 1.4265x; 1.4216x over previous
#include <cuda_runtime.h>
#include <cuda_bf16.h>
#include <math.h>
#include <stdint.h>

#define L    512
#define T    96
#define CIN  150
#define HID  150
#define J3   450
#define J3P  480
#define KW   5

// TC-GEMM geometry for xi
#define KPAD   832            // 5 taps * 160 + pad (13 chunks of 64)
#define KC     64
#define NKC    13
#define RPAD   520
#define CPAD   160
#define NB     512

// ---------------- scratch ----------------
__device__ float g_xi [(size_t)T * L * J3P];
__device__ float g_ys0[(size_t)L * T * HID];
__device__ float g_hh5[KW * L * J3];
__device__ float g_h  [2 * L * HID];
__device__ __align__(256) __nv_bfloat16 g_xtp_hi[(size_t)T * RPAD * CPAD];
__device__ __align__(256) __nv_bfloat16 g_xtp_lo[(size_t)T * RPAD * CPAD];
__device__ __align__(256) __nv_bfloat16 g_B_hi[(size_t)NB * KPAD];
__device__ __align__(256) __nv_bfloat16 g_B_lo[(size_t)NB * KPAD];

extern __shared__ float smem[];

// ---------------- PTX helpers (baseline ISA only) ----------------
__device__ __forceinline__ uint32_t smem_u32(const void* p) {
    uint32_t a;
    asm("{ .reg .u64 t; cvta.to.shared.u64 t, %1; cvt.u32.u64 %0, t; }" : "=r"(a) : "l"(p));
    return a;
}
#define CP_ASYNC16(dst, src) \
    asm volatile("cp.async.cg.shared.global [%0], [%1], 16;" :: "r"(dst), "l"(src))
#define CP_COMMIT() asm volatile("cp.async.commit_group;")
#define CP_WAIT1()  asm volatile("cp.async.wait_group 1;")
#define CP_WAIT0()  asm volatile("cp.async.wait_group 0;")
#define LDSM_X4(r0,r1,r2,r3,a) \
    asm volatile("ldmatrix.sync.aligned.m8n8.x4.shared.b16 {%0,%1,%2,%3}, [%4];" \
        : "=r"(r0),"=r"(r1),"=r"(r2),"=r"(r3) : "r"(a))
#define MMA16816(d,a0,a1,a2,a3,b0,b1) \
    asm volatile("mma.sync.aligned.m16n8k16.row.col.f32.bf16.bf16.f32 " \
        "{%0,%1,%2,%3},{%4,%5,%6,%7},{%8,%9},{%0,%1,%2,%3};" \
        : "+f"((d)[0]),"+f"((d)[1]),"+f"((d)[2]),"+f"((d)[3]) \
        : "r"(a0),"r"(a1),"r"(a2),"r"(a3),"r"(b0),"r"(b1))

// =====================================================================
// prep: fp32 -> bf16 hi/lo split, padded layouts for the MMA GEMM
// =====================================================================
__global__ void prep_x_kernel(const float* __restrict__ x) {
    size_t i = (size_t)blockIdx.x * blockDim.x + threadIdx.x;
    const size_t Ntot = (size_t)T * RPAD * CPAD;
    if (i >= Ntot) return;
    int c = i % CPAD;
    int r = (i / CPAD) % RPAD;
    int t = i / ((size_t)CPAD * RPAD);
    float v = 0.f;
    if (r >= 2 && r < 2 + L && c < CIN)
        v = x[(((size_t)(r - 2)) * T + t) * CIN + c];
    __nv_bfloat16 hi = __float2bfloat16(v);
    __nv_bfloat16 lo = __float2bfloat16(v - __bfloat162float(hi));
    g_xtp_hi[i] = hi;
    g_xtp_lo[i] = lo;
}

__global__ void prep_w_kernel(const float* __restrict__ Wi) {
    size_t i = (size_t)blockIdx.x * blockDim.x + threadIdx.x;
    const size_t Ntot = (size_t)NB * KPAD;
    if (i >= Ntot) return;
    int k = i % KPAD;
    int n = i / KPAD;
    int tap = k / CPAD, c = k % CPAD;
    float v = 0.f;
    if (n < J3 && tap < KW && c < CIN)
        v = Wi[((size_t)tap * CIN + c) * J3 + n];
    __nv_bfloat16 hi = __float2bfloat16(v);
    __nv_bfloat16 lo = __float2bfloat16(v - __bfloat162float(hi));
    g_B_hi[i] = hi;
    g_B_lo[i] = lo;
}

// =====================================================================
// xi via mma.sync bf16 split: grid (96 t, 4 m, 4 n), 256 thr.
// Block tile 128x128, warp tile 32x64, K = 13 chunks of 64, cp.async DB.
// smem chunk layout: [A_hi 16K][A_lo 16K][B_hi 16K][B_lo 16K] x2 buffers.
// =====================================================================
#define BUFSZ 65536

__global__ __launch_bounds__(256, 1) void xi_mma_kernel(
    const float* __restrict__ bi, float* __restrict__ xi)
{
    char* sm = reinterpret_cast<char*>(smem);
    const uint32_t smb = smem_u32(sm);
    const int tid = threadIdx.x;
    const int lane = tid & 31, wid = tid >> 5;
    const int t = blockIdx.x, mblk = blockIdx.y, nblk = blockIdx.z;

    const int mw = wid & 3, nw = wid >> 2;
    const int m0 = mw * 32, n0 = nw * 64;

    // per-lane ldmatrix address components
    int aRow[2], aXor[2];
    const int jA = (lane >> 4) & 1;
    #pragma unroll
    for (int mt = 0; mt < 2; mt++) {
        aRow[mt] = (m0 + mt * 16 + (lane & 15)) * 128;
        aXor[mt] = ((m0 + mt * 16 + (lane & 15)) & 7);
    }
    int bRow[4], bXor[4];
    const int jB = (lane >> 3) & 1;
    #pragma unroll
    for (int np = 0; np < 4; np++) {
        int r = n0 + np * 16 + (lane & 7) + ((lane >> 4) & 1) * 8;
        bRow[np] = r * 128;
        bXor[np] = r & 7;
    }

    // staging source bases
    const __nv_bfloat16* srcA_hi = g_xtp_hi + ((size_t)t * RPAD + (size_t)mblk * 128) * CPAD;
    const __nv_bfloat16* srcA_lo = g_xtp_lo + ((size_t)t * RPAD + (size_t)mblk * 128) * CPAD;
    const __nv_bfloat16* srcB_hi = g_B_hi + (size_t)nblk * 128 * KPAD;
    const __nv_bfloat16* srcB_lo = g_B_lo + (size_t)nblk * 128 * KPAD;

    // per-thread staging assignment: 16 transfers/chunk
    // u in [0,4096): arr = u>>10, row = (u&1023)>>3, seg = u&7
    float acc[2][8][4];
    #pragma unroll
    for (int mt = 0; mt < 2; mt++)
        #pragma unroll
        for (int nt = 0; nt < 8; nt++)
            #pragma unroll
            for (int k = 0; k < 4; k++) acc[mt][nt][k] = 0.f;

    auto stage = [&](int kc, int buf) {
        const uint32_t base = smb + buf * BUFSZ;
        #pragma unroll
        for (int it = 0; it < 16; it++) {
            int u = it * 256 + tid;
            int arr = u >> 10;
            int v = u & 1023;
            int row = v >> 3, seg = v & 7;
            const __nv_bfloat16* src;
            if (arr == 0)      src = srcA_hi + (size_t)row * CPAD + kc * KC + seg * 8;
            else if (arr == 1) src = srcA_lo + (size_t)row * CPAD + kc * KC + seg * 8;
            else if (arr == 2) src = srcB_hi + (size_t)row * KPAD + kc * KC + seg * 8;
            else               src = srcB_lo + (size_t)row * KPAD + kc * KC + seg * 8;
            uint32_t dst = base + arr * 16384 + row * 128 + ((seg ^ (row & 7)) << 4);
            CP_ASYNC16(dst, src);
        }
    };

    stage(0, 0);
    CP_COMMIT();

    for (int kc = 0; kc < NKC; kc++) {
        const int buf = kc & 1;
        if (kc + 1 < NKC) {
            stage(kc + 1, buf ^ 1);
            CP_COMMIT();
            CP_WAIT1();
        } else {
            CP_WAIT0();
        }
        __syncthreads();

        const uint32_t bA_hi = smb + buf * BUFSZ;
        const uint32_t bA_lo = bA_hi + 16384;
        const uint32_t bB_hi = bA_hi + 32768;
        const uint32_t bB_lo = bA_hi + 49152;

        #pragma unroll
        for (int ks = 0; ks < 4; ks++) {
            uint32_t ah[2][4], al[2][4];
            #pragma unroll
            for (int mt = 0; mt < 2; mt++) {
                uint32_t off = aRow[mt] + (((2 * ks + jA) ^ aXor[mt]) << 4);
                LDSM_X4(ah[mt][0], ah[mt][1], ah[mt][2], ah[mt][3], bA_hi + off);
                LDSM_X4(al[mt][0], al[mt][1], al[mt][2], al[mt][3], bA_lo + off);
            }
            #pragma unroll
            for (int np = 0; np < 4; np++) {
                uint32_t off = bRow[np] + (((2 * ks + jB) ^ bXor[np]) << 4);
                uint32_t bh[4], bl[4];
                LDSM_X4(bh[0], bh[1], bh[2], bh[3], bB_hi + off);
                LDSM_X4(bl[0], bl[1], bl[2], bl[3], bB_lo + off);
                #pragma unroll
                for (int mt = 0; mt < 2; mt++) {
                    float* d0 = acc[mt][np * 2];
                    float* d1 = acc[mt][np * 2 + 1];
                    MMA16816(d0, ah[mt][0], ah[mt][1], ah[mt][2], ah[mt][3], bh[0], bh[1]);
                    MMA16816(d0, al[mt][0], al[mt][1], al[mt][2], al[mt][3], bh[0], bh[1]);
                    MMA16816(d0, ah[mt][0], ah[mt][1], ah[mt][2], ah[mt][3], bl[0], bl[1]);
                    MMA16816(d1, ah[mt][0], ah[mt][1], ah[mt][2], ah[mt][3], bh[2], bh[3]);
                    MMA16816(d1, al[mt][0], al[mt][1], al[mt][2], al[mt][3], bh[2], bh[3]);
                    MMA16816(d1, ah[mt][0], ah[mt][1], ah[mt][2], ah[mt][3], bl[2], bl[3]);
                }
            }
        }
        __syncthreads();
    }

    // ---- epilogue ----
    const int g  = lane >> 2;
    const int tq = lane & 3;
    #pragma unroll
    for (int mt = 0; mt < 2; mt++) {
        int r0 = mblk * 128 + m0 + mt * 16 + g;
        int r1 = r0 + 8;
        float* row0 = xi + ((size_t)t * L + r0) * J3P;
        float* row1 = xi + ((size_t)t * L + r1) * J3P;
        #pragma unroll
        for (int nt = 0; nt < 8; nt++) {
            int j0 = nblk * 128 + n0 + nt * 8 + tq * 2;
            if (j0 < J3) {
                float b0 = bi[j0], b1 = bi[j0 + 1];
                float2 v0 = make_float2(acc[mt][nt][0] + b0, acc[mt][nt][1] + b1);
                float2 v1 = make_float2(acc[mt][nt][2] + b0, acc[mt][nt][3] + b1);
                *reinterpret_cast<float2*>(row0 + j0) = v0;
                *reinterpret_cast<float2*>(row1 + j0) = v1;
            }
        }
    }
}

// =====================================================================
// Recurrent path — proven R1 fp32 per-step kernels (xi stride -> J3P)
// =====================================================================
#define BL   64
#define BJ   50
#define TY   16
#define TX   10
#define NTHR (TY * TX)

__global__ void zero_kernel(float* __restrict__ p, int n) {
    int i = blockIdx.x * blockDim.x + threadIdx.x;
    if (i < n) p[i] = 0.f;
}

__global__ __launch_bounds__(NTHR) void s1_kernel(
    const float* __restrict__ h,
    const float* __restrict__ Wh,
    float* __restrict__ hh5)
{
    float* sh_h = smem;
    float* sh_w = smem + BL * HID;

    const int tap = blockIdx.z;
    const int l0  = blockIdx.y * BL;
    const int j0  = blockIdx.x * BJ;
    const int tid = threadIdx.x;
    const int ty = tid / TX;
    const int tx = tid % TX;

    for (int idx = tid; idx < BL * HID; idx += NTHR) {
        int r = idx / HID, c = idx % HID;
        int l = l0 + r + tap - 2;
        sh_h[idx] = (l >= 0 && l < L) ? h[l * HID + c] : 0.f;
    }
    for (int idx = tid; idx < HID * BJ; idx += NTHR) {
        int c = idx / BJ, j = idx % BJ;
        sh_w[idx] = Wh[((size_t)tap * HID + c) * J3 + j0 + j];
    }
    __syncthreads();

    float acc[4][5];
    #pragma unroll
    for (int i = 0; i < 4; i++)
        #pragma unroll
        for (int j = 0; j < 5; j++) acc[i][j] = 0.f;

    #pragma unroll 2
    for (int c = 0; c < HID; c++) {
        float a[4], b[5];
        #pragma unroll
        for (int i = 0; i < 4; i++)
            a[i] = sh_h[(ty * 4 + i) * HID + c];
        #pragma unroll
        for (int j = 0; j < 5; j++)
            b[j] = sh_w[c * BJ + tx * 5 + j];
        #pragma unroll
        for (int i = 0; i < 4; i++)
            #pragma unroll
            for (int j = 0; j < 5; j++)
                acc[i][j] += a[i] * b[j];
    }

    #pragma unroll
    for (int i = 0; i < 4; i++) {
        int l = l0 + ty * 4 + i;
        #pragma unroll
        for (int j = 0; j < 5; j++)
            hh5[((size_t)tap * L + l) * J3 + j0 + tx * 5 + j] = acc[i][j];
    }
}

__global__ void s2_kernel(
    const float* __restrict__ xi_t,   // (L, J3P) slice for this t
    const float* __restrict__ hh5,
    const float* __restrict__ h_in,
    float* __restrict__ h_out,
    float* __restrict__ ys,
    int t)
{
    int idx = blockIdx.x * blockDim.x + threadIdx.x;
    if (idx >= L * HID) return;
    int l = idx / HID, c = idx % HID;

    float hr = 0.f, hz = 0.f, hn = 0.f;
    #pragma unroll
    for (int tap = 0; tap < KW; tap++) {
        const float* p = hh5 + ((size_t)tap * L + l) * J3;
        hr += p[c];
        hz += p[c + HID];
        hn += p[c + 2 * HID];
    }
    const float* q = xi_t + (size_t)l * J3P;
    float xr = q[c], xz = q[c + HID], xn = q[c + 2 * HID];

    float r = 1.f / (1.f + expf(-(xr + hr)));
    float z = 1.f / (1.f + expf(-(xz + hz)));
    float n = tanhf(xn + r * hn);
    float hnew = (1.f - z) * n + z * h_in[idx];

    h_out[idx] = hnew;
    ys[((size_t)l * T + t) * HID + c] = hnew;
}

// =====================================================================
extern "C" void kernel_launch(void* const* d_in, const int* in_sizes, int n_in,
                              void* d_out, int out_size)
{
    (void)in_sizes; (void)n_in; (void)out_size;
    const float* xs  = (const float*)d_in[0];
    const float* Wi0 = (const float*)d_in[1];
    const float* bi0 = (const float*)d_in[2];
    const float* Wh0 = (const float*)d_in[3];
    const float* Wi1 = (const float*)d_in[4];
    const float* bi1 = (const float*)d_in[5];
    const float* Wh1 = (const float*)d_in[6];
    float* out = (float*)d_out;

    float *xi, *ys0, *hh5, *h;
    cudaGetSymbolAddress((void**)&xi,  g_xi);
    cudaGetSymbolAddress((void**)&ys0, g_ys0);
    cudaGetSymbolAddress((void**)&hh5, g_hh5);
    cudaGetSymbolAddress((void**)&h,   g_h);

    const size_t smem_s1  = (BL * HID + HID * BJ) * sizeof(float);   // 68400 B
    const size_t smem_mma = 2 * BUFSZ;                               // 131072 B
    static int attr_done = 0;
    if (!attr_done) {
        cudaFuncSetAttribute(s1_kernel, cudaFuncAttributeMaxDynamicSharedMemorySize, 73728);
        cudaFuncSetAttribute(xi_mma_kernel, cudaFuncAttributeMaxDynamicSharedMemorySize, (int)smem_mma);
        attr_done = 1;
    }

    const size_t n_prep_x = (size_t)T * RPAD * CPAD;
    const int    gx = (int)((n_prep_x + 255) / 256);
    const size_t n_prep_w = (size_t)NB * KPAD;
    const int    gw = (int)((n_prep_w + 255) / 256);
    const dim3 grid_mma(T, 4, 4);
    const dim3 grid_s1(J3 / BJ, L / BL, KW);
    const int  n_h = L * HID;
    const int  gate_blocks = (n_h + 255) / 256;

    for (int layer = 0; layer < 2; layer++) {
        const float* x  = layer ? (const float*)ys0 : xs;
        const float* Wi = layer ? Wi1 : Wi0;
        const float* bi = layer ? bi1 : bi0;
        const float* Wh = layer ? Wh1 : Wh0;
        float*       ys = layer ? out : ys0;

        prep_x_kernel<<<gx, 256>>>(x);
        prep_w_kernel<<<gw, 256>>>(Wi);
        xi_mma_kernel<<<grid_mma, 256, smem_mma>>>(bi, xi);

        zero_kernel<<<gate_blocks, 256>>>(h, n_h);
        int cur = 0;
        for (int t = 0; t < T; t++) {
            s1_kernel<<<grid_s1, NTHR, smem_s1>>>(h + cur * n_h, Wh, hh5);
            s2_kernel<<<gate_blocks, 256>>>(xi + (size_t)t * L * J3P, hh5,
                                            h + cur * n_h, h + (1 - cur) * n_h,
                                            ys, t);
            cur ^= 1;
        }
    }
}

// round 6
// speedup vs baseline: 2.8227x; 1.9788x over previous
#include <cuda_runtime.h>
#include <cuda_bf16.h>
#include <math.h>
#include <stdint.h>

#define L    512
#define T    96
#define CIN  150
#define HID  150
#define J3   450
#define J3P  480
#define KW   5

// padded GEMM geometry (flat sliding-window im2col)
#define KPAD   832            // 5 taps * 160 + pad -> 13 chunks of 64
#define KC     64
#define NKC    13
#define RPAD   520            // 512 + 8 pad rows (2 front)
#define CPAD   160
#define NB     512            // xi B padded N

// ---------------- scratch ----------------
__device__ float g_xi [(size_t)T * L * J3P];
__device__ unsigned g_cnt;
__device__ volatile unsigned g_gen;
__device__ __align__(256) __nv_bfloat16 g_xtp_hi[(size_t)T * RPAD * CPAD];
__device__ __align__(256) __nv_bfloat16 g_xtp_lo[(size_t)T * RPAD * CPAD];
__device__ __align__(256) __nv_bfloat16 g_B_hi[(size_t)NB * KPAD];
__device__ __align__(256) __nv_bfloat16 g_B_lo[(size_t)NB * KPAD];
// recurrent
__device__ __align__(256) __nv_bfloat16 g_hp_hi[2][RPAD * CPAD];
__device__ __align__(256) __nv_bfloat16 g_hp_lo[2][RPAD * CPAD];
__device__ float g_hfp[2][L * HID];
__device__ __align__(256) __nv_bfloat16 g_Br_hi[480 * KPAD];
__device__ __align__(256) __nv_bfloat16 g_Br_lo[480 * KPAD];

extern __shared__ float smem[];

// ---------------- PTX helpers (baseline ISA only) ----------------
__device__ __forceinline__ uint32_t smem_u32(const void* p) {
    uint32_t a;
    asm("{ .reg .u64 t; cvta.to.shared.u64 t, %1; cvt.u32.u64 %0, t; }" : "=r"(a) : "l"(p));
    return a;
}
#define CP_ASYNC16(dst, src) \
    asm volatile("cp.async.cg.shared.global [%0], [%1], 16;" :: "r"(dst), "l"(src))
#define CP_COMMIT() asm volatile("cp.async.commit_group;")
#define CP_WAIT1()  asm volatile("cp.async.wait_group 1;")
#define CP_WAIT0()  asm volatile("cp.async.wait_group 0;")
#define LDSM_X4(r0,r1,r2,r3,a) \
    asm volatile("ldmatrix.sync.aligned.m8n8.x4.shared.b16 {%0,%1,%2,%3}, [%4];" \
        : "=r"(r0),"=r"(r1),"=r"(r2),"=r"(r3) : "r"(a))
#define MMA16816(d,a0,a1,a2,a3,b0,b1) \
    asm volatile("mma.sync.aligned.m16n8k16.row.col.f32.bf16.bf16.f32 " \
        "{%0,%1,%2,%3},{%4,%5,%6,%7},{%8,%9},{%0,%1,%2,%3};" \
        : "+f"((d)[0]),"+f"((d)[1]),"+f"((d)[2]),"+f"((d)[3]) \
        : "r"(a0),"r"(a1),"r"(a2),"r"(a3),"r"(b0),"r"(b1))

__device__ __forceinline__ float sigf(float x) {
    float e = __expf(-x);
    return __fdividef(1.f, 1.f + e);
}
__device__ __forceinline__ float tanhfast(float x) {
    return 2.f * sigf(2.f * x) - 1.f;
}

// =====================================================================
// prep kernels
// =====================================================================
__global__ void prep_x_kernel(const float* __restrict__ x) {
    size_t i = (size_t)blockIdx.x * blockDim.x + threadIdx.x;
    const size_t Ntot = (size_t)T * RPAD * CPAD;
    if (i >= Ntot) return;
    int c = i % CPAD;
    int r = (i / CPAD) % RPAD;
    int t = i / ((size_t)CPAD * RPAD);
    float v = 0.f;
    if (r >= 2 && r < 2 + L && c < CIN)
        v = x[(((size_t)(r - 2)) * T + t) * CIN + c];
    __nv_bfloat16 hi = __float2bfloat16(v);
    __nv_bfloat16 lo = __float2bfloat16(v - __bfloat162float(hi));
    g_xtp_hi[i] = hi;
    g_xtp_lo[i] = lo;
}

__global__ void prep_w_kernel(const float* __restrict__ Wi) {
    size_t i = (size_t)blockIdx.x * blockDim.x + threadIdx.x;
    const size_t Ntot = (size_t)NB * KPAD;
    if (i >= Ntot) return;
    int k = i % KPAD;
    int n = i / KPAD;
    int tap = k / CPAD, c = k % CPAD;
    float v = 0.f;
    if (n < J3 && tap < KW && c < CIN)
        v = Wi[((size_t)tap * CIN + c) * J3 + n];
    __nv_bfloat16 hi = __float2bfloat16(v);
    __nv_bfloat16 lo = __float2bfloat16(v - __bfloat162float(hi));
    g_B_hi[i] = hi;
    g_B_lo[i] = lo;
}

// recurrent weights, gate-grouped: row n = cg*32 + j, j<30: gate=j/10, ch=j%10
__global__ void prep_wrec_kernel(const float* __restrict__ Wh) {
    size_t i = (size_t)blockIdx.x * blockDim.x + threadIdx.x;
    const size_t Ntot = (size_t)480 * KPAD;
    if (i >= Ntot) return;
    int k = i % KPAD;
    int n = i / KPAD;
    int cg = n >> 5, j = n & 31;
    int tap = k / CPAD, c = k % CPAD;
    float v = 0.f;
    if (j < 30 && tap < KW && c < CIN) {
        int gate = j / 10, ch = j - gate * 10;
        v = Wh[((size_t)tap * CIN + c) * J3 + gate * HID + cg * 10 + ch];
    }
    __nv_bfloat16 hi = __float2bfloat16(v);
    __nv_bfloat16 lo = __float2bfloat16(v - __bfloat162float(hi));
    g_Br_hi[i] = hi;
    g_Br_lo[i] = lo;
}

// zero hp ping-pong (both) + hfp (both)
__global__ void zero_rec_kernel() {
    int i = blockIdx.x * blockDim.x + threadIdx.x;
    if (i < RPAD * CPAD) {
        __nv_bfloat16 z = __float2bfloat16(0.f);
        g_hp_hi[0][i] = z; g_hp_hi[1][i] = z;
        g_hp_lo[0][i] = z; g_hp_lo[1][i] = z;
    }
    if (i < L * HID) {
        g_hfp[0][i] = 0.f; g_hfp[1][i] = 0.f;
    }
}

__global__ void init_barrier() { g_cnt = 0u; g_gen = 0u; }

// =====================================================================
// xi via mma.sync bf16 split (proven in R5): grid (96,4,4), 256 thr.
// =====================================================================
#define BUFSZ 65536

__global__ __launch_bounds__(256, 1) void xi_mma_kernel(
    const float* __restrict__ bi, float* __restrict__ xi)
{
    char* sm = reinterpret_cast<char*>(smem);
    const uint32_t smb = smem_u32(sm);
    const int tid = threadIdx.x;
    const int lane = tid & 31, wid = tid >> 5;
    const int t = blockIdx.x, mblk = blockIdx.y, nblk = blockIdx.z;

    const int mw = wid & 3, nw = wid >> 2;
    const int m0 = mw * 32, n0 = nw * 64;

    int aRow[2], aXor[2];
    const int jA = (lane >> 4) & 1;
    #pragma unroll
    for (int mt = 0; mt < 2; mt++) {
        aRow[mt] = (m0 + mt * 16 + (lane & 15)) * 128;
        aXor[mt] = ((m0 + mt * 16 + (lane & 15)) & 7);
    }
    int bRow[4], bXor[4];
    const int jB = (lane >> 3) & 1;
    #pragma unroll
    for (int np = 0; np < 4; np++) {
        int r = n0 + np * 16 + (lane & 7) + ((lane >> 4) & 1) * 8;
        bRow[np] = r * 128;
        bXor[np] = r & 7;
    }

    const __nv_bfloat16* srcA_hi = g_xtp_hi + ((size_t)t * RPAD + (size_t)mblk * 128) * CPAD;
    const __nv_bfloat16* srcA_lo = g_xtp_lo + ((size_t)t * RPAD + (size_t)mblk * 128) * CPAD;
    const __nv_bfloat16* srcB_hi = g_B_hi + (size_t)nblk * 128 * KPAD;
    const __nv_bfloat16* srcB_lo = g_B_lo + (size_t)nblk * 128 * KPAD;

    float acc[2][8][4];
    #pragma unroll
    for (int mt = 0; mt < 2; mt++)
        #pragma unroll
        for (int nt = 0; nt < 8; nt++)
            #pragma unroll
            for (int k = 0; k < 4; k++) acc[mt][nt][k] = 0.f;

    auto stage = [&](int kc, int buf) {
        const uint32_t base = smb + buf * BUFSZ;
        #pragma unroll
        for (int it = 0; it < 16; it++) {
            int u = it * 256 + tid;
            int arr = u >> 10;
            int v = u & 1023;
            int row = v >> 3, seg = v & 7;
            const __nv_bfloat16* src;
            if (arr == 0)      src = srcA_hi + (size_t)row * CPAD + kc * KC + seg * 8;
            else if (arr == 1) src = srcA_lo + (size_t)row * CPAD + kc * KC + seg * 8;
            else if (arr == 2) src = srcB_hi + (size_t)row * KPAD + kc * KC + seg * 8;
            else               src = srcB_lo + (size_t)row * KPAD + kc * KC + seg * 8;
            uint32_t dst = base + arr * 16384 + row * 128 + ((seg ^ (row & 7)) << 4);
            CP_ASYNC16(dst, src);
        }
    };

    stage(0, 0);
    CP_COMMIT();

    for (int kc = 0; kc < NKC; kc++) {
        const int buf = kc & 1;
        if (kc + 1 < NKC) {
            stage(kc + 1, buf ^ 1);
            CP_COMMIT();
            CP_WAIT1();
        } else {
            CP_WAIT0();
        }
        __syncthreads();

        const uint32_t bA_hi = smb + buf * BUFSZ;
        const uint32_t bA_lo = bA_hi + 16384;
        const uint32_t bB_hi = bA_hi + 32768;
        const uint32_t bB_lo = bA_hi + 49152;

        #pragma unroll
        for (int ks = 0; ks < 4; ks++) {
            uint32_t ah[2][4], al[2][4];
            #pragma unroll
            for (int mt = 0; mt < 2; mt++) {
                uint32_t off = aRow[mt] + (((2 * ks + jA) ^ aXor[mt]) << 4);
                LDSM_X4(ah[mt][0], ah[mt][1], ah[mt][2], ah[mt][3], bA_hi + off);
                LDSM_X4(al[mt][0], al[mt][1], al[mt][2], al[mt][3], bA_lo + off);
            }
            #pragma unroll
            for (int np = 0; np < 4; np++) {
                uint32_t off = bRow[np] + (((2 * ks + jB) ^ bXor[np]) << 4);
                uint32_t bh[4], bl[4];
                LDSM_X4(bh[0], bh[1], bh[2], bh[3], bB_hi + off);
                LDSM_X4(bl[0], bl[1], bl[2], bl[3], bB_lo + off);
                #pragma unroll
                for (int mt = 0; mt < 2; mt++) {
                    float* d0 = acc[mt][np * 2];
                    float* d1 = acc[mt][np * 2 + 1];
                    MMA16816(d0, ah[mt][0], ah[mt][1], ah[mt][2], ah[mt][3], bh[0], bh[1]);
                    MMA16816(d0, al[mt][0], al[mt][1], al[mt][2], al[mt][3], bh[0], bh[1]);
                    MMA16816(d0, ah[mt][0], ah[mt][1], ah[mt][2], ah[mt][3], bl[0], bl[1]);
                    MMA16816(d1, ah[mt][0], ah[mt][1], ah[mt][2], ah[mt][3], bh[2], bh[3]);
                    MMA16816(d1, al[mt][0], al[mt][1], al[mt][2], al[mt][3], bh[2], bh[3]);
                    MMA16816(d1, ah[mt][0], ah[mt][1], ah[mt][2], ah[mt][3], bl[2], bl[3]);
                }
            }
        }
        __syncthreads();
    }

    const int g  = lane >> 2;
    const int tq = lane & 3;
    #pragma unroll
    for (int mt = 0; mt < 2; mt++) {
        int r0 = mblk * 128 + m0 + mt * 16 + g;
        int r1 = r0 + 8;
        float* row0 = xi + ((size_t)t * L + r0) * J3P;
        float* row1 = xi + ((size_t)t * L + r1) * J3P;
        #pragma unroll
        for (int nt = 0; nt < 8; nt++) {
            int j0 = nblk * 128 + n0 + nt * 8 + tq * 2;
            if (j0 < J3) {
                float b0 = bi[j0], b1 = bi[j0 + 1];
                float2 v0 = make_float2(acc[mt][nt][0] + b0, acc[mt][nt][1] + b1);
                float2 v1 = make_float2(acc[mt][nt][2] + b0, acc[mt][nt][3] + b1);
                *reinterpret_cast<float2*>(row0 + j0) = v0;
                *reinterpret_cast<float2*>(row1 + j0) = v1;
            }
        }
    }
}

// =====================================================================
// Persistent recurrent MMA kernel.
// grid (15 cg, 8 mg) = 120 blocks, 128 thr (4 warps).
// Block tile: 64 rows x 32 cols ({r,z,n} x 10 channels + 2 pad).
// Weights (32 x 832 hi/lo) resident in smem; A double-buffered cp.async.
// One grid barrier per step (ping-pong h buffers).
// =====================================================================
#define NBLK 120
#define SM_RB_HI 0
#define SM_RB_LO 53248
#define SM_RA    106496
#define SM_RHH   139264
#define SM_REC_TOTAL 147456

__device__ __forceinline__ void grid_barrier(unsigned target) {
    __threadfence();
    __syncthreads();
    if (threadIdx.x == 0) {
        unsigned a = atomicAdd(&g_cnt, 1u);
        if (a == NBLK - 1u) {
            g_cnt = 0u;
            __threadfence();
            g_gen = target;
        } else {
            while (g_gen < target) { }
            __threadfence();
        }
    }
    __syncthreads();
}

__global__ __launch_bounds__(128, 1) void rec_mma_kernel(
    const float* __restrict__ xi, float* __restrict__ outp, int layer)
{
    char* sm = reinterpret_cast<char*>(smem);
    const uint32_t smb = smem_u32(sm);
    float* sh_hh = reinterpret_cast<float*>(sm + SM_RHH);
    const int tid = threadIdx.x;
    const int lane = tid & 31, wid = tid >> 5;
    const int cg = blockIdx.x, mg = blockIdx.y;
    const int c0 = cg * 10;
    const int l0 = mg * 64;

    const int mw = wid & 1, nw = wid >> 1;
    const int m0w = mw * 32, n0w = nw * 16;

    // ldmatrix address components (constant over steps)
    int aRow[2], aXor[2];
    const int jA = (lane >> 4) & 1;
    #pragma unroll
    for (int mt = 0; mt < 2; mt++) {
        int r = m0w + mt * 16 + (lane & 15);
        aRow[mt] = r * 128;
        aXor[mt] = r & 7;
    }
    const int bR = n0w + (lane & 7) + ((lane >> 4) & 1) * 8;
    const int bXor = bR & 7;
    const int jB = (lane >> 3) & 1;

    // ---- load resident B (weights) once ----
    for (int u = tid; u < 6656; u += 128) {
        int arr = u / 3328;
        int v = u - arr * 3328;
        int chunk = v >> 8;
        int w = v & 255;
        int row = w >> 3, seg = w & 7;
        const __nv_bfloat16* src =
            (arr ? g_Br_lo : g_Br_hi) + ((size_t)(cg * 32 + row)) * KPAD + chunk * KC + seg * 8;
        uint32_t dst = smb + (arr ? SM_RB_LO : SM_RB_HI)
                     + chunk * 4096 + row * 128 + ((seg ^ (row & 7)) << 4);
        CP_ASYNC16(dst, src);
    }
    CP_COMMIT();
    CP_WAIT0();
    __syncthreads();

    unsigned bar = 1;

    for (int t = 0; t < T; t++) {
        const int cur = t & 1;
        const __nv_bfloat16* hp_hi = g_hp_hi[cur];
        const __nv_bfloat16* hp_lo = g_hp_lo[cur];

        float acc[2][2][4];
        #pragma unroll
        for (int mt = 0; mt < 2; mt++)
            #pragma unroll
            for (int nt = 0; nt < 2; nt++)
                #pragma unroll
                for (int k = 0; k < 4; k++) acc[mt][nt][k] = 0.f;

        // A staging lambda: 1024 xfers (hi+lo, 64 rows, 8 segs)
        auto stageA = [&](int kc, int buf) {
            #pragma unroll
            for (int it = 0; it < 8; it++) {
                int u = it * 128 + tid;
                int arr = u >> 9;
                int v = u & 511;
                int row = v >> 3, seg = v & 7;
                const __nv_bfloat16* src =
                    (arr ? hp_lo : hp_hi) + (size_t)(l0 + row) * CPAD + kc * KC + seg * 8;
                uint32_t dst = smb + SM_RA + buf * 16384 + arr * 8192
                             + row * 128 + ((seg ^ (row & 7)) << 4);
                CP_ASYNC16(dst, src);
            }
        };

        stageA(0, 0);
        CP_COMMIT();

        for (int kc = 0; kc < NKC; kc++) {
            const int buf = kc & 1;
            if (kc + 1 < NKC) {
                stageA(kc + 1, buf ^ 1);
                CP_COMMIT();
                CP_WAIT1();
            } else {
                CP_WAIT0();
            }
            __syncthreads();

            const uint32_t bAh = smb + SM_RA + buf * 16384;
            const uint32_t bAl = bAh + 8192;
            const uint32_t bBh = smb + SM_RB_HI + kc * 4096;
            const uint32_t bBl = smb + SM_RB_LO + kc * 4096;
            const uint32_t bRowOff = bR * 128;

            #pragma unroll
            for (int ks = 0; ks < 4; ks++) {
                uint32_t ah[2][4], al[2][4];
                #pragma unroll
                for (int mt = 0; mt < 2; mt++) {
                    uint32_t off = aRow[mt] + (((2 * ks + jA) ^ aXor[mt]) << 4);
                    LDSM_X4(ah[mt][0], ah[mt][1], ah[mt][2], ah[mt][3], bAh + off);
                    LDSM_X4(al[mt][0], al[mt][1], al[mt][2], al[mt][3], bAl + off);
                }
                uint32_t boff = bRowOff + (((2 * ks + jB) ^ bXor) << 4);
                uint32_t bh[4], bl[4];
                LDSM_X4(bh[0], bh[1], bh[2], bh[3], bBh + boff);
                LDSM_X4(bl[0], bl[1], bl[2], bl[3], bBl + boff);
                #pragma unroll
                for (int mt = 0; mt < 2; mt++) {
                    float* d0 = acc[mt][0];
                    float* d1 = acc[mt][1];
                    MMA16816(d0, ah[mt][0], ah[mt][1], ah[mt][2], ah[mt][3], bh[0], bh[1]);
                    MMA16816(d0, al[mt][0], al[mt][1], al[mt][2], al[mt][3], bh[0], bh[1]);
                    MMA16816(d0, ah[mt][0], ah[mt][1], ah[mt][2], ah[mt][3], bl[0], bl[1]);
                    MMA16816(d1, ah[mt][0], ah[mt][1], ah[mt][2], ah[mt][3], bh[2], bh[3]);
                    MMA16816(d1, al[mt][0], al[mt][1], al[mt][2], al[mt][3], bh[2], bh[3]);
                    MMA16816(d1, ah[mt][0], ah[mt][1], ah[mt][2], ah[mt][3], bl[2], bl[3]);
                }
            }
            __syncthreads();
        }

        // ---- stage hh into smem ----
        {
            const int g = lane >> 2, tq = lane & 3;
            #pragma unroll
            for (int mt = 0; mt < 2; mt++) {
                int r0 = m0w + mt * 16 + g;
                int r1 = r0 + 8;
                #pragma unroll
                for (int nt = 0; nt < 2; nt++) {
                    int col = n0w + nt * 8 + tq * 2;
                    sh_hh[r0 * 32 + col]     = acc[mt][nt][0];
                    sh_hh[r0 * 32 + col + 1] = acc[mt][nt][1];
                    sh_hh[r1 * 32 + col]     = acc[mt][nt][2];
                    sh_hh[r1 * 32 + col + 1] = acc[mt][nt][3];
                }
            }
        }
        __syncthreads();

        // ---- gate epilogue: 64 rows x 10 channels ----
        {
            const float* hfp_cur = g_hfp[cur];
            float* hfp_nxt = g_hfp[cur ^ 1];
            __nv_bfloat16* hpn_hi = g_hp_hi[cur ^ 1];
            __nv_bfloat16* hpn_lo = g_hp_lo[cur ^ 1];
            const float* xit = xi + ((size_t)t * L) * J3P;

            for (int e = tid; e < 640; e += 128) {
                int lr = e / 10, ch = e - lr * 10;
                int l = l0 + lr, c = c0 + ch;
                float hr = sh_hh[lr * 32 + ch];
                float hz = sh_hh[lr * 32 + 10 + ch];
                float hn = sh_hh[lr * 32 + 20 + ch];
                const float* q = xit + (size_t)l * J3P;
                float xr = q[c], xz = q[HID + c], xn = q[2 * HID + c];
                float hp = hfp_cur[l * HID + c];
                float r = sigf(xr + hr);
                float z = sigf(xz + hz);
                float n = tanhfast(xn + r * hn);
                float hnew = n + z * (hp - n);

                hfp_nxt[l * HID + c] = hnew;
                __nv_bfloat16 hi = __float2bfloat16(hnew);
                __nv_bfloat16 lo = __float2bfloat16(hnew - __bfloat162float(hi));
                size_t hpidx = (size_t)(l + 2) * CPAD + c;
                hpn_hi[hpidx] = hi;
                hpn_lo[hpidx] = lo;

                if (layer == 0) {
                    size_t xidx = ((size_t)t * RPAD + (l + 2)) * CPAD + c;
                    g_xtp_hi[xidx] = hi;
                    g_xtp_lo[xidx] = lo;
                } else {
                    outp[((size_t)l * T + t) * HID + c] = hnew;
                }
            }
        }

        if (t + 1 < T) grid_barrier(bar++);
    }
}

// =====================================================================
extern "C" void kernel_launch(void* const* d_in, const int* in_sizes, int n_in,
                              void* d_out, int out_size)
{
    (void)in_sizes; (void)n_in; (void)out_size;
    const float* xs  = (const float*)d_in[0];
    const float* Wi0 = (const float*)d_in[1];
    const float* bi0 = (const float*)d_in[2];
    const float* Wh0 = (const float*)d_in[3];
    const float* Wi1 = (const float*)d_in[4];
    const float* bi1 = (const float*)d_in[5];
    const float* Wh1 = (const float*)d_in[6];
    float* out = (float*)d_out;

    float* xi;
    cudaGetSymbolAddress((void**)&xi, g_xi);

    const size_t smem_mma = 2 * BUFSZ;
    static int attr_done = 0;
    if (!attr_done) {
        cudaFuncSetAttribute(xi_mma_kernel, cudaFuncAttributeMaxDynamicSharedMemorySize, (int)smem_mma);
        cudaFuncSetAttribute(rec_mma_kernel, cudaFuncAttributeMaxDynamicSharedMemorySize, SM_REC_TOTAL);
        attr_done = 1;
    }

    const size_t n_prep_x = (size_t)T * RPAD * CPAD;
    const int    gx = (int)((n_prep_x + 255) / 256);
    const size_t n_prep_w = (size_t)NB * KPAD;
    const int    gw = (int)((n_prep_w + 255) / 256);
    const size_t n_prep_wr = (size_t)480 * KPAD;
    const int    gwr = (int)((n_prep_wr + 255) / 256);
    const int    gz = (RPAD * CPAD + 255) / 256;
    const dim3 grid_mma(T, 4, 4);
    const dim3 grid_rec(15, 8);

    for (int layer = 0; layer < 2; layer++) {
        const float* Wi = layer ? Wi1 : Wi0;
        const float* bi = layer ? bi1 : bi0;
        const float* Wh = layer ? Wh1 : Wh0;

        if (layer == 0) prep_x_kernel<<<gx, 256>>>(xs);
        prep_w_kernel<<<gw, 256>>>(Wi);
        prep_wrec_kernel<<<gwr, 256>>>(Wh);
        xi_mma_kernel<<<grid_mma, 256, smem_mma>>>(bi, xi);
        zero_rec_kernel<<<gz, 256>>>();
        init_barrier<<<1, 1>>>();
        rec_mma_kernel<<<grid_rec, 128, SM_REC_TOTAL>>>(xi, out, layer);
    }
}

// round 7
// speedup vs baseline: 3.0923x; 1.0955x over previous
#include <cuda_runtime.h>
#include <cuda_bf16.h>
#include <math.h>
#include <stdint.h>

#define L    512
#define T    96
#define CIN  150
#define HID  150
#define J3   450
#define J3P  480
#define KW   5

// padded GEMM geometry (flat sliding-window im2col)
#define CPAD   152            // padded channel stride (150 + 2)
#define KPAD   768            // 5*152 = 760 -> pad to 768 = 12 chunks of 64
#define KC     64
#define NKC    12
#define RPAD   520
#define NB     512            // xi B padded N

// ---------------- scratch ----------------
__device__ float g_xi [(size_t)T * L * J3P];
__device__ volatile unsigned g_sync[8];
__device__ __align__(256) __nv_bfloat16 g_xtp_hi[(size_t)T * RPAD * CPAD];
__device__ __align__(256) __nv_bfloat16 g_xtp_lo[(size_t)T * RPAD * CPAD];
__device__ __align__(256) __nv_bfloat16 g_B_hi[(size_t)NB * KPAD];
__device__ __align__(256) __nv_bfloat16 g_B_lo[(size_t)NB * KPAD];
// recurrent
__device__ __align__(256) __nv_bfloat16 g_hp_hi[2][RPAD * CPAD];
__device__ __align__(256) __nv_bfloat16 g_hp_lo[2][RPAD * CPAD];
__device__ float g_hfp[2][L * HID];
__device__ __align__(256) __nv_bfloat16 g_Br_hi[480 * KPAD];
__device__ __align__(256) __nv_bfloat16 g_Br_lo[480 * KPAD];

extern __shared__ float smem[];

// ---------------- PTX helpers (baseline ISA only) ----------------
__device__ __forceinline__ uint32_t smem_u32(const void* p) {
    uint32_t a;
    asm("{ .reg .u64 t; cvta.to.shared.u64 t, %1; cvt.u32.u64 %0, t; }" : "=r"(a) : "l"(p));
    return a;
}
#define CP_ASYNC16(dst, src) \
    asm volatile("cp.async.cg.shared.global [%0], [%1], 16;" :: "r"(dst), "l"(src))
#define CP_COMMIT() asm volatile("cp.async.commit_group;")
#define CP_WAIT1()  asm volatile("cp.async.wait_group 1;")
#define CP_WAIT0()  asm volatile("cp.async.wait_group 0;")
#define LDSM_X4(r0,r1,r2,r3,a) \
    asm volatile("ldmatrix.sync.aligned.m8n8.x4.shared.b16 {%0,%1,%2,%3}, [%4];" \
        : "=r"(r0),"=r"(r1),"=r"(r2),"=r"(r3) : "r"(a))
#define MMA16816(d,a0,a1,a2,a3,b0,b1) \
    asm volatile("mma.sync.aligned.m16n8k16.row.col.f32.bf16.bf16.f32 " \
        "{%0,%1,%2,%3},{%4,%5,%6,%7},{%8,%9},{%0,%1,%2,%3};" \
        : "+f"((d)[0]),"+f"((d)[1]),"+f"((d)[2]),"+f"((d)[3]) \
        : "r"(a0),"r"(a1),"r"(a2),"r"(a3),"r"(b0),"r"(b1))

__device__ __forceinline__ float sigf(float x) {
    float e = __expf(-x);
    return __fdividef(1.f, 1.f + e);
}
__device__ __forceinline__ float tanhfast(float x) {
    return 2.f * sigf(2.f * x) - 1.f;
}

// =====================================================================
// prep kernels
// =====================================================================
__global__ void prep_x_kernel(const float* __restrict__ x) {
    size_t i = (size_t)blockIdx.x * blockDim.x + threadIdx.x;
    const size_t Ntot = (size_t)T * RPAD * CPAD;
    if (i >= Ntot) return;
    int c = i % CPAD;
    int r = (i / CPAD) % RPAD;
    int t = i / ((size_t)CPAD * RPAD);
    float v = 0.f;
    if (r >= 2 && r < 2 + L && c < CIN)
        v = x[(((size_t)(r - 2)) * T + t) * CIN + c];
    __nv_bfloat16 hi = __float2bfloat16(v);
    __nv_bfloat16 lo = __float2bfloat16(v - __bfloat162float(hi));
    g_xtp_hi[i] = hi;
    g_xtp_lo[i] = lo;
}

__global__ void prep_w_kernel(const float* __restrict__ Wi) {
    size_t i = (size_t)blockIdx.x * blockDim.x + threadIdx.x;
    const size_t Ntot = (size_t)NB * KPAD;
    if (i >= Ntot) return;
    int k = i % KPAD;
    int n = i / KPAD;
    int tap = k / CPAD, c = k % CPAD;
    float v = 0.f;
    if (n < J3 && tap < KW && c < CIN)
        v = Wi[((size_t)tap * CIN + c) * J3 + n];
    __nv_bfloat16 hi = __float2bfloat16(v);
    __nv_bfloat16 lo = __float2bfloat16(v - __bfloat162float(hi));
    g_B_hi[i] = hi;
    g_B_lo[i] = lo;
}

// recurrent weights, gate-grouped: row n = cg*32 + j, j<30: gate=j/10, ch=j%10
__global__ void prep_wrec_kernel(const float* __restrict__ Wh) {
    size_t i = (size_t)blockIdx.x * blockDim.x + threadIdx.x;
    const size_t Ntot = (size_t)480 * KPAD;
    if (i >= Ntot) return;
    int k = i % KPAD;
    int n = i / KPAD;
    int cg = n >> 5, j = n & 31;
    int tap = k / CPAD, c = k % CPAD;
    float v = 0.f;
    if (j < 30 && tap < KW && c < CIN) {
        int gate = j / 10, ch = j - gate * 10;
        v = Wh[((size_t)tap * CIN + c) * J3 + gate * HID + cg * 10 + ch];
    }
    __nv_bfloat16 hi = __float2bfloat16(v);
    __nv_bfloat16 lo = __float2bfloat16(v - __bfloat162float(hi));
    g_Br_hi[i] = hi;
    g_Br_lo[i] = lo;
}

__global__ void zero_rec_kernel() {
    int i = blockIdx.x * blockDim.x + threadIdx.x;
    if (i < RPAD * CPAD) {
        __nv_bfloat16 z = __float2bfloat16(0.f);
        g_hp_hi[0][i] = z; g_hp_hi[1][i] = z;
        g_hp_lo[0][i] = z; g_hp_lo[1][i] = z;
    }
    if (i < L * HID) {
        g_hfp[0][i] = 0.f; g_hfp[1][i] = 0.f;
    }
    if (i < 8) g_sync[i] = 0u;
}

// =====================================================================
// xi via mma.sync bf16 split: grid (96,4,4), 256 thr.
// =====================================================================
#define BUFSZ 65536

__global__ __launch_bounds__(256, 1) void xi_mma_kernel(
    const float* __restrict__ bi, float* __restrict__ xi)
{
    char* sm = reinterpret_cast<char*>(smem);
    const uint32_t smb = smem_u32(sm);
    const int tid = threadIdx.x;
    const int lane = tid & 31, wid = tid >> 5;
    const int t = blockIdx.x, mblk = blockIdx.y, nblk = blockIdx.z;

    const int mw = wid & 3, nw = wid >> 2;
    const int m0 = mw * 32, n0 = nw * 64;

    int aRow[2], aXor[2];
    const int jA = (lane >> 4) & 1;
    #pragma unroll
    for (int mt = 0; mt < 2; mt++) {
        aRow[mt] = (m0 + mt * 16 + (lane & 15)) * 128;
        aXor[mt] = ((m0 + mt * 16 + (lane & 15)) & 7);
    }
    int bRow[4], bXor[4];
    const int jB = (lane >> 3) & 1;
    #pragma unroll
    for (int np = 0; np < 4; np++) {
        int r = n0 + np * 16 + (lane & 7) + ((lane >> 4) & 1) * 8;
        bRow[np] = r * 128;
        bXor[np] = r & 7;
    }

    const __nv_bfloat16* srcA_hi = g_xtp_hi + ((size_t)t * RPAD + (size_t)mblk * 128) * CPAD;
    const __nv_bfloat16* srcA_lo = g_xtp_lo + ((size_t)t * RPAD + (size_t)mblk * 128) * CPAD;
    const __nv_bfloat16* srcB_hi = g_B_hi + (size_t)nblk * 128 * KPAD;
    const __nv_bfloat16* srcB_lo = g_B_lo + (size_t)nblk * 128 * KPAD;

    float acc[2][8][4];
    #pragma unroll
    for (int mt = 0; mt < 2; mt++)
        #pragma unroll
        for (int nt = 0; nt < 8; nt++)
            #pragma unroll
            for (int k = 0; k < 4; k++) acc[mt][nt][k] = 0.f;

    auto stage = [&](int kc, int buf) {
        const uint32_t base = smb + buf * BUFSZ;
        #pragma unroll
        for (int it = 0; it < 16; it++) {
            int u = it * 256 + tid;
            int arr = u >> 10;
            int v = u & 1023;
            int row = v >> 3, seg = v & 7;
            const __nv_bfloat16* src;
            if (arr == 0)      src = srcA_hi + (size_t)row * CPAD + kc * KC + seg * 8;
            else if (arr == 1) src = srcA_lo + (size_t)row * CPAD + kc * KC + seg * 8;
            else if (arr == 2) src = srcB_hi + (size_t)row * KPAD + kc * KC + seg * 8;
            else               src = srcB_lo + (size_t)row * KPAD + kc * KC + seg * 8;
            uint32_t dst = base + arr * 16384 + row * 128 + ((seg ^ (row & 7)) << 4);
            CP_ASYNC16(dst, src);
        }
    };

    stage(0, 0);
    CP_COMMIT();

    for (int kc = 0; kc < NKC; kc++) {
        const int buf = kc & 1;
        if (kc + 1 < NKC) {
            stage(kc + 1, buf ^ 1);
            CP_COMMIT();
            CP_WAIT1();
        } else {
            CP_WAIT0();
        }
        __syncthreads();

        const uint32_t bA_hi = smb + buf * BUFSZ;
        const uint32_t bA_lo = bA_hi + 16384;
        const uint32_t bB_hi = bA_hi + 32768;
        const uint32_t bB_lo = bA_hi + 49152;

        #pragma unroll
        for (int ks = 0; ks < 4; ks++) {
            uint32_t ah[2][4], al[2][4];
            #pragma unroll
            for (int mt = 0; mt < 2; mt++) {
                uint32_t off = aRow[mt] + (((2 * ks + jA) ^ aXor[mt]) << 4);
                LDSM_X4(ah[mt][0], ah[mt][1], ah[mt][2], ah[mt][3], bA_hi + off);
                LDSM_X4(al[mt][0], al[mt][1], al[mt][2], al[mt][3], bA_lo + off);
            }
            #pragma unroll
            for (int np = 0; np < 4; np++) {
                uint32_t off = bRow[np] + (((2 * ks + jB) ^ bXor[np]) << 4);
                uint32_t bh[4], bl[4];
                LDSM_X4(bh[0], bh[1], bh[2], bh[3], bB_hi + off);
                LDSM_X4(bl[0], bl[1], bl[2], bl[3], bB_lo + off);
                #pragma unroll
                for (int mt = 0; mt < 2; mt++) {
                    float* d0 = acc[mt][np * 2];
                    float* d1 = acc[mt][np * 2 + 1];
                    MMA16816(d0, ah[mt][0], ah[mt][1], ah[mt][2], ah[mt][3], bh[0], bh[1]);
                    MMA16816(d0, al[mt][0], al[mt][1], al[mt][2], al[mt][3], bh[0], bh[1]);
                    MMA16816(d0, ah[mt][0], ah[mt][1], ah[mt][2], ah[mt][3], bl[0], bl[1]);
                    MMA16816(d1, ah[mt][0], ah[mt][1], ah[mt][2], ah[mt][3], bh[2], bh[3]);
                    MMA16816(d1, al[mt][0], al[mt][1], al[mt][2], al[mt][3], bh[2], bh[3]);
                    MMA16816(d1, ah[mt][0], ah[mt][1], ah[mt][2], ah[mt][3], bl[2], bl[3]);
                }
            }
        }
        __syncthreads();
    }

    const int g  = lane >> 2;
    const int tq = lane & 3;
    #pragma unroll
    for (int mt = 0; mt < 2; mt++) {
        int r0 = mblk * 128 + m0 + mt * 16 + g;
        int r1 = r0 + 8;
        float* row0 = xi + ((size_t)t * L + r0) * J3P;
        float* row1 = xi + ((size_t)t * L + r1) * J3P;
        #pragma unroll
        for (int nt = 0; nt < 8; nt++) {
            int j0 = nblk * 128 + n0 + nt * 8 + tq * 2;
            if (j0 < J3) {
                float b0 = bi[j0], b1 = bi[j0 + 1];
                float2 v0 = make_float2(acc[mt][nt][0] + b0, acc[mt][nt][1] + b1);
                float2 v1 = make_float2(acc[mt][nt][2] + b0, acc[mt][nt][3] + b1);
                *reinterpret_cast<float2*>(row0 + j0) = v0;
                *reinterpret_cast<float2*>(row1 + j0) = v1;
            }
        }
    }
}

// =====================================================================
// Persistent recurrent MMA kernel, v2.
// grid (15 cg, 8 mg) = 120 blocks, 256 thr (8 warps, 4mw x 2nw).
// Block tile 64 rows x 32 cols; warp tile 16x16.
// Weights resident in smem; A double-buffered cp.async; neighbor sync.
// =====================================================================
#define SM_RB_HI 0
#define SM_RB_LO 49152
#define SM_RA    98304
#define SM_RHH   131072
#define SM_REC_TOTAL 139264

__global__ __launch_bounds__(256, 1) void rec_mma_kernel(
    const float* __restrict__ xi, float* __restrict__ outp, int layer)
{
    char* sm = reinterpret_cast<char*>(smem);
    const uint32_t smb = smem_u32(sm);
    float* sh_hh = reinterpret_cast<float*>(sm + SM_RHH);
    const int tid = threadIdx.x;
    const int lane = tid & 31, wid = tid >> 5;
    const int cg = blockIdx.x, mg = blockIdx.y;
    const int c0 = cg * 10;
    const int l0 = mg * 64;

    const int mw = wid & 3, nw = wid >> 2;   // 4 x 2 warps
    const int m0w = mw * 16, n0w = nw * 16;

    // ldmatrix address components (constant over steps)
    const int arA = m0w + (lane & 15);
    const int aRow = arA * 128;
    const int aXor = arA & 7;
    const int jA = (lane >> 4) & 1;
    const int bR = n0w + (lane & 7) + ((lane >> 4) & 1) * 8;
    const int bRowOff = bR * 128;
    const int bXor = bR & 7;
    const int jB = (lane >> 3) & 1;

    // ---- load resident B (weights) once: 2 arr x 12 chunks x 32 rows x 8 segs ----
    for (int u = tid; u < 6144; u += 256) {
        int arr = u / 3072;
        int v = u - arr * 3072;
        int chunk = v >> 8;
        int w = v & 255;
        int row = w >> 3, seg = w & 7;
        const __nv_bfloat16* src =
            (arr ? g_Br_lo : g_Br_hi) + ((size_t)(cg * 32 + row)) * KPAD + chunk * KC + seg * 8;
        uint32_t dst = smb + (arr ? SM_RB_LO : SM_RB_HI)
                     + chunk * 4096 + row * 128 + ((seg ^ (row & 7)) << 4);
        CP_ASYNC16(dst, src);
    }
    CP_COMMIT();
    CP_WAIT0();
    __syncthreads();

    for (int t = 0; t < T; t++) {
        const int cur = t & 1;
        const __nv_bfloat16* hp_hi = g_hp_hi[cur];
        const __nv_bfloat16* hp_lo = g_hp_lo[cur];

        // neighbor sync: wait for mg-1, mg, mg+1 to finish step t-1
        if (t > 0) {
            if (tid < 3) {
                int mgn = mg + tid - 1;
                if (mgn < 0) mgn = 0;
                if (mgn > 7) mgn = 7;
                const unsigned tgt = 15u * (unsigned)t;
                while (g_sync[mgn] < tgt) { }
            }
            __syncthreads();
        }

        float acc[4][2][4];   // [mw-local? no: per-warp mt=1] -> acc[nt][4] per warp; use [2][4]
        // per warp: 16 rows x 16 cols -> acc[2 n-tiles][4]
        float a0[2][4];
        #pragma unroll
        for (int nt = 0; nt < 2; nt++)
            #pragma unroll
            for (int k = 0; k < 4; k++) a0[nt][k] = 0.f;
        (void)acc;

        // A staging: 2 arr x 64 rows x 8 segs = 1024 xfers / 256 thr = 4
        auto stageA = [&](int kc, int buf) {
            #pragma unroll
            for (int it = 0; it < 4; it++) {
                int u = it * 256 + tid;
                int arr = u >> 9;
                int v = u & 511;
                int row = v >> 3, seg = v & 7;
                const __nv_bfloat16* src =
                    (arr ? hp_lo : hp_hi) + (size_t)(l0 + row) * CPAD + kc * KC + seg * 8;
                uint32_t dst = smb + SM_RA + buf * 16384 + arr * 8192
                             + row * 128 + ((seg ^ (row & 7)) << 4);
                CP_ASYNC16(dst, src);
            }
        };

        stageA(0, 0);
        CP_COMMIT();

        for (int kc = 0; kc < NKC; kc++) {
            const int buf = kc & 1;
            if (kc + 1 < NKC) {
                stageA(kc + 1, buf ^ 1);
                CP_COMMIT();
                CP_WAIT1();
            } else {
                CP_WAIT0();
            }
            __syncthreads();

            const uint32_t bAh = smb + SM_RA + buf * 16384;
            const uint32_t bAl = bAh + 8192;
            const uint32_t bBh = smb + SM_RB_HI + kc * 4096;
            const uint32_t bBl = smb + SM_RB_LO + kc * 4096;

            #pragma unroll
            for (int ks = 0; ks < 4; ks++) {
                uint32_t ah[4], al[4];
                uint32_t off = aRow + (((2 * ks + jA) ^ aXor) << 4);
                LDSM_X4(ah[0], ah[1], ah[2], ah[3], bAh + off);
                LDSM_X4(al[0], al[1], al[2], al[3], bAl + off);
                uint32_t boff = bRowOff + (((2 * ks + jB) ^ bXor) << 4);
                uint32_t bh[4], bl[4];
                LDSM_X4(bh[0], bh[1], bh[2], bh[3], bBh + boff);
                LDSM_X4(bl[0], bl[1], bl[2], bl[3], bBl + boff);
                float* d0 = a0[0];
                float* d1 = a0[1];
                MMA16816(d0, ah[0], ah[1], ah[2], ah[3], bh[0], bh[1]);
                MMA16816(d0, al[0], al[1], al[2], al[3], bh[0], bh[1]);
                MMA16816(d0, ah[0], ah[1], ah[2], ah[3], bl[0], bl[1]);
                MMA16816(d1, ah[0], ah[1], ah[2], ah[3], bh[2], bh[3]);
                MMA16816(d1, al[0], al[1], al[2], al[3], bh[2], bh[3]);
                MMA16816(d1, ah[0], ah[1], ah[2], ah[3], bl[2], bl[3]);
            }
            __syncthreads();
        }

        // ---- stage hh into smem ----
        {
            const int g = lane >> 2, tq = lane & 3;
            int r0 = m0w + g;
            int r1 = r0 + 8;
            #pragma unroll
            for (int nt = 0; nt < 2; nt++) {
                int col = n0w + nt * 8 + tq * 2;
                sh_hh[r0 * 32 + col]     = a0[nt][0];
                sh_hh[r0 * 32 + col + 1] = a0[nt][1];
                sh_hh[r1 * 32 + col]     = a0[nt][2];
                sh_hh[r1 * 32 + col + 1] = a0[nt][3];
            }
        }
        __syncthreads();

        // ---- gate epilogue: 64 rows x 10 channels ----
        {
            const float* hfp_cur = g_hfp[cur];
            float* hfp_nxt = g_hfp[cur ^ 1];
            __nv_bfloat16* hpn_hi = g_hp_hi[cur ^ 1];
            __nv_bfloat16* hpn_lo = g_hp_lo[cur ^ 1];
            const float* xit = xi + ((size_t)t * L) * J3P;

            for (int e = tid; e < 640; e += 256) {
                int lr = e / 10, ch = e - lr * 10;
                int l = l0 + lr, c = c0 + ch;
                float hr = sh_hh[lr * 32 + ch];
                float hz = sh_hh[lr * 32 + 10 + ch];
                float hn = sh_hh[lr * 32 + 20 + ch];
                const float* q = xit + (size_t)l * J3P;
                float xr = q[c], xz = q[HID + c], xn = q[2 * HID + c];
                float hp = hfp_cur[l * HID + c];
                float r = sigf(xr + hr);
                float z = sigf(xz + hz);
                float n = tanhfast(xn + r * hn);
                float hnew = n + z * (hp - n);

                hfp_nxt[l * HID + c] = hnew;
                __nv_bfloat16 hi = __float2bfloat16(hnew);
                __nv_bfloat16 lo = __float2bfloat16(hnew - __bfloat162float(hi));
                size_t hpidx = (size_t)(l + 2) * CPAD + c;
                hpn_hi[hpidx] = hi;
                hpn_lo[hpidx] = lo;

                if (layer == 0) {
                    size_t xidx = ((size_t)t * RPAD + (l + 2)) * CPAD + c;
                    g_xtp_hi[xidx] = hi;
                    g_xtp_lo[xidx] = lo;
                } else {
                    outp[((size_t)l * T + t) * HID + c] = hnew;
                }
            }
        }

        // signal completion of step t
        __threadfence();
        __syncthreads();
        if (tid == 0) atomicAdd((unsigned*)&g_sync[mg], 1u);
    }
}

// =====================================================================
extern "C" void kernel_launch(void* const* d_in, const int* in_sizes, int n_in,
                              void* d_out, int out_size)
{
    (void)in_sizes; (void)n_in; (void)out_size;
    const float* xs  = (const float*)d_in[0];
    const float* Wi0 = (const float*)d_in[1];
    const float* bi0 = (const float*)d_in[2];
    const float* Wh0 = (const float*)d_in[3];
    const float* Wi1 = (const float*)d_in[4];
    const float* bi1 = (const float*)d_in[5];
    const float* Wh1 = (const float*)d_in[6];
    float* out = (float*)d_out;

    float* xi;
    cudaGetSymbolAddress((void**)&xi, g_xi);

    const size_t smem_mma = 2 * BUFSZ;
    static int attr_done = 0;
    if (!attr_done) {
        cudaFuncSetAttribute(xi_mma_kernel, cudaFuncAttributeMaxDynamicSharedMemorySize, (int)smem_mma);
        cudaFuncSetAttribute(rec_mma_kernel, cudaFuncAttributeMaxDynamicSharedMemorySize, SM_REC_TOTAL);
        attr_done = 1;
    }

    const size_t n_prep_x = (size_t)T * RPAD * CPAD;
    const int    gx = (int)((n_prep_x + 255) / 256);
    const size_t n_prep_w = (size_t)NB * KPAD;
    const int    gw = (int)((n_prep_w + 255) / 256);
    const size_t n_prep_wr = (size_t)480 * KPAD;
    const int    gwr = (int)((n_prep_wr + 255) / 256);
    const int    gz = (RPAD * CPAD + 255) / 256;
    const dim3 grid_mma(T, 4, 4);
    const dim3 grid_rec(15, 8);

    for (int layer = 0; layer < 2; layer++) {
        const float* Wi = layer ? Wi1 : Wi0;
        const float* bi = layer ? bi1 : bi0;
        const float* Wh = layer ? Wh1 : Wh0;

        if (layer == 0) prep_x_kernel<<<gx, 256>>>(xs);
        prep_w_kernel<<<gw, 256>>>(Wi);
        prep_wrec_kernel<<<gwr, 256>>>(Wh);
        xi_mma_kernel<<<grid_mma, 256, smem_mma>>>(bi, xi);
        zero_rec_kernel<<<gz, 256>>>();
        rec_mma_kernel<<<grid_rec, 256, SM_REC_TOTAL>>>(xi, out, layer);
    }
}

// round 9
// speedup vs baseline: 3.7411x; 1.2098x over previous
#include <cuda_runtime.h>
#include <cuda_bf16.h>
#include <math.h>
#include <stdint.h>

#define L    512
#define T    96
#define CIN  150
#define HID  150
#define J3   450
#define J3P  480
#define KW   5

// padded GEMM geometry (flat sliding-window im2col)
#define CPAD   152            // padded channel stride (150 + 2)
#define KPAD   768            // 5*152 = 760 -> pad to 768 = 12 chunks of 64
#define KC     64
#define NKC    12
#define RPAD   520
#define NB     512            // xi B padded N

// ---------------- scratch ----------------
__device__ float g_xi [(size_t)T * L * J3P];
__device__ volatile unsigned g_sync[8];
__device__ __align__(256) __nv_bfloat16 g_xtp_hi[(size_t)T * RPAD * CPAD];
__device__ __align__(256) __nv_bfloat16 g_xtp_lo[(size_t)T * RPAD * CPAD];
__device__ __align__(256) __nv_bfloat16 g_B_hi[(size_t)NB * KPAD];
__device__ __align__(256) __nv_bfloat16 g_B_lo[(size_t)NB * KPAD];
// recurrent
__device__ __align__(256) __nv_bfloat16 g_hp_hi[2][RPAD * CPAD];
__device__ __align__(256) __nv_bfloat16 g_hp_lo[2][RPAD * CPAD];
__device__ float g_hfp[2][L * HID];
__device__ __align__(256) __nv_bfloat16 g_Br_hi[480 * KPAD];
__device__ __align__(256) __nv_bfloat16 g_Br_lo[480 * KPAD];

extern __shared__ float smem[];

// ---------------- PTX helpers (baseline ISA only) ----------------
__device__ __forceinline__ uint32_t smem_u32(const void* p) {
    uint32_t a;
    asm("{ .reg .u64 t; cvta.to.shared.u64 t, %1; cvt.u32.u64 %0, t; }" : "=r"(a) : "l"(p));
    return a;
}
#define CP_ASYNC16(dst, src) \
    asm volatile("cp.async.cg.shared.global [%0], [%1], 16;" :: "r"(dst), "l"(src))
#define CP_COMMIT() asm volatile("cp.async.commit_group;")
#define CP_WAIT1()  asm volatile("cp.async.wait_group 1;")
#define CP_WAIT0()  asm volatile("cp.async.wait_group 0;")
#define LDSM_X4(r0,r1,r2,r3,a) \
    asm volatile("ldmatrix.sync.aligned.m8n8.x4.shared.b16 {%0,%1,%2,%3}, [%4];" \
        : "=r"(r0),"=r"(r1),"=r"(r2),"=r"(r3) : "r"(a))
#define MMA16816(d,a0,a1,a2,a3,b0,b1) \
    asm volatile("mma.sync.aligned.m16n8k16.row.col.f32.bf16.bf16.f32 " \
        "{%0,%1,%2,%3},{%4,%5,%6,%7},{%8,%9},{%0,%1,%2,%3};" \
        : "+f"((d)[0]),"+f"((d)[1]),"+f"((d)[2]),"+f"((d)[3]) \
        : "r"(a0),"r"(a1),"r"(a2),"r"(a3),"r"(b0),"r"(b1))

__device__ __forceinline__ float sigf(float x) {
    float e = __expf(-x);
    return __fdividef(1.f, 1.f + e);
}
__device__ __forceinline__ float tanhfast(float x) {
    return 2.f * sigf(2.f * x) - 1.f;
}

// =====================================================================
// prep kernels
// =====================================================================
__global__ void prep_x_kernel(const float* __restrict__ x) {
    size_t i = (size_t)blockIdx.x * blockDim.x + threadIdx.x;
    const size_t Ntot = (size_t)T * RPAD * CPAD;
    if (i >= Ntot) return;
    int c = i % CPAD;
    int r = (i / CPAD) % RPAD;
    int t = i / ((size_t)CPAD * RPAD);
    float v = 0.f;
    if (r >= 2 && r < 2 + L && c < CIN)
        v = x[(((size_t)(r - 2)) * T + t) * CIN + c];
    __nv_bfloat16 hi = __float2bfloat16(v);
    __nv_bfloat16 lo = __float2bfloat16(v - __bfloat162float(hi));
    g_xtp_hi[i] = hi;
    g_xtp_lo[i] = lo;
}

__global__ void prep_w_kernel(const float* __restrict__ Wi) {
    size_t i = (size_t)blockIdx.x * blockDim.x + threadIdx.x;
    const size_t Ntot = (size_t)NB * KPAD;
    if (i >= Ntot) return;
    int k = i % KPAD;
    int n = i / KPAD;
    int tap = k / CPAD, c = k % CPAD;
    float v = 0.f;
    if (n < J3 && tap < KW && c < CIN)
        v = Wi[((size_t)tap * CIN + c) * J3 + n];
    __nv_bfloat16 hi = __float2bfloat16(v);
    __nv_bfloat16 lo = __float2bfloat16(v - __bfloat162float(hi));
    g_B_hi[i] = hi;
    g_B_lo[i] = lo;
}

// recurrent weights, gate-grouped: row n = cg*32 + j, j<30: gate=j/10, ch=j%10
__global__ void prep_wrec_kernel(const float* __restrict__ Wh) {
    size_t i = (size_t)blockIdx.x * blockDim.x + threadIdx.x;
    const size_t Ntot = (size_t)480 * KPAD;
    if (i >= Ntot) return;
    int k = i % KPAD;
    int n = i / KPAD;
    int cg = n >> 5, j = n & 31;
    int tap = k / CPAD, c = k % CPAD;
    float v = 0.f;
    if (j < 30 && tap < KW && c < CIN) {
        int gate = j / 10, ch = j - gate * 10;
        v = Wh[((size_t)tap * CIN + c) * J3 + gate * HID + cg * 10 + ch];
    }
    __nv_bfloat16 hi = __float2bfloat16(v);
    __nv_bfloat16 lo = __float2bfloat16(v - __bfloat162float(hi));
    g_Br_hi[i] = hi;
    g_Br_lo[i] = lo;
}

__global__ void zero_rec_kernel() {
    int i = blockIdx.x * blockDim.x + threadIdx.x;
    if (i < RPAD * CPAD) {
        __nv_bfloat16 z = __float2bfloat16(0.f);
        g_hp_hi[0][i] = z; g_hp_hi[1][i] = z;
        g_hp_lo[0][i] = z; g_hp_lo[1][i] = z;
    }
    if (i < L * HID) {
        g_hfp[0][i] = 0.f; g_hfp[1][i] = 0.f;
    }
    if (i < 8) g_sync[i] = 0u;
}

// =====================================================================
// xi via mma.sync bf16 split: grid (96,4,4), 256 thr. (proven)
// =====================================================================
#define BUFSZ 65536

__global__ __launch_bounds__(256, 1) void xi_mma_kernel(
    const float* __restrict__ bi, float* __restrict__ xi)
{
    char* sm = reinterpret_cast<char*>(smem);
    const uint32_t smb = smem_u32(sm);
    const int tid = threadIdx.x;
    const int lane = tid & 31, wid = tid >> 5;
    const int t = blockIdx.x, mblk = blockIdx.y, nblk = blockIdx.z;

    const int mw = wid & 3, nw = wid >> 2;
    const int m0 = mw * 32, n0 = nw * 64;

    int aRow[2], aXor[2];
    const int jA = (lane >> 4) & 1;
    #pragma unroll
    for (int mt = 0; mt < 2; mt++) {
        aRow[mt] = (m0 + mt * 16 + (lane & 15)) * 128;
        aXor[mt] = ((m0 + mt * 16 + (lane & 15)) & 7);
    }
    int bRow[4], bXor[4];
    const int jB = (lane >> 3) & 1;
    #pragma unroll
    for (int np = 0; np < 4; np++) {
        int r = n0 + np * 16 + (lane & 7) + ((lane >> 4) & 1) * 8;
        bRow[np] = r * 128;
        bXor[np] = r & 7;
    }

    const __nv_bfloat16* srcA_hi = g_xtp_hi + ((size_t)t * RPAD + (size_t)mblk * 128) * CPAD;
    const __nv_bfloat16* srcA_lo = g_xtp_lo + ((size_t)t * RPAD + (size_t)mblk * 128) * CPAD;
    const __nv_bfloat16* srcB_hi = g_B_hi + (size_t)nblk * 128 * KPAD;
    const __nv_bfloat16* srcB_lo = g_B_lo + (size_t)nblk * 128 * KPAD;

    float acc[2][8][4];
    #pragma unroll
    for (int mt = 0; mt < 2; mt++)
        #pragma unroll
        for (int nt = 0; nt < 8; nt++)
            #pragma unroll
            for (int k = 0; k < 4; k++) acc[mt][nt][k] = 0.f;

    auto stage = [&](int kc, int buf) {
        const uint32_t base = smb + buf * BUFSZ;
        #pragma unroll
        for (int it = 0; it < 16; it++) {
            int u = it * 256 + tid;
            int arr = u >> 10;
            int v = u & 1023;
            int row = v >> 3, seg = v & 7;
            const __nv_bfloat16* src;
            if (arr == 0)      src = srcA_hi + (size_t)row * CPAD + kc * KC + seg * 8;
            else if (arr == 1) src = srcA_lo + (size_t)row * CPAD + kc * KC + seg * 8;
            else if (arr == 2) src = srcB_hi + (size_t)row * KPAD + kc * KC + seg * 8;
            else               src = srcB_lo + (size_t)row * KPAD + kc * KC + seg * 8;
            uint32_t dst = base + arr * 16384 + row * 128 + ((seg ^ (row & 7)) << 4);
            CP_ASYNC16(dst, src);
        }
    };

    stage(0, 0);
    CP_COMMIT();

    for (int kc = 0; kc < NKC; kc++) {
        const int buf = kc & 1;
        if (kc + 1 < NKC) {
            stage(kc + 1, buf ^ 1);
            CP_COMMIT();
            CP_WAIT1();
        } else {
            CP_WAIT0();
        }
        __syncthreads();

        const uint32_t bA_hi = smb + buf * BUFSZ;
        const uint32_t bA_lo = bA_hi + 16384;
        const uint32_t bB_hi = bA_hi + 32768;
        const uint32_t bB_lo = bA_hi + 49152;

        #pragma unroll
        for (int ks = 0; ks < 4; ks++) {
            uint32_t ah[2][4], al[2][4];
            #pragma unroll
            for (int mt = 0; mt < 2; mt++) {
                uint32_t off = aRow[mt] + (((2 * ks + jA) ^ aXor[mt]) << 4);
                LDSM_X4(ah[mt][0], ah[mt][1], ah[mt][2], ah[mt][3], bA_hi + off);
                LDSM_X4(al[mt][0], al[mt][1], al[mt][2], al[mt][3], bA_lo + off);
            }
            #pragma unroll
            for (int np = 0; np < 4; np++) {
                uint32_t off = bRow[np] + (((2 * ks + jB) ^ bXor[np]) << 4);
                uint32_t bh[4], bl[4];
                LDSM_X4(bh[0], bh[1], bh[2], bh[3], bB_hi + off);
                LDSM_X4(bl[0], bl[1], bl[2], bl[3], bB_lo + off);
                #pragma unroll
                for (int mt = 0; mt < 2; mt++) {
                    float* d0 = acc[mt][np * 2];
                    float* d1 = acc[mt][np * 2 + 1];
                    MMA16816(d0, ah[mt][0], ah[mt][1], ah[mt][2], ah[mt][3], bh[0], bh[1]);
                    MMA16816(d0, al[mt][0], al[mt][1], al[mt][2], al[mt][3], bh[0], bh[1]);
                    MMA16816(d0, ah[mt][0], ah[mt][1], ah[mt][2], ah[mt][3], bl[0], bl[1]);
                    MMA16816(d1, ah[mt][0], ah[mt][1], ah[mt][2], ah[mt][3], bh[2], bh[3]);
                    MMA16816(d1, al[mt][0], al[mt][1], al[mt][2], al[mt][3], bh[2], bh[3]);
                    MMA16816(d1, ah[mt][0], ah[mt][1], ah[mt][2], ah[mt][3], bl[2], bl[3]);
                }
            }
        }
        __syncthreads();
    }

    const int g  = lane >> 2;
    const int tq = lane & 3;
    #pragma unroll
    for (int mt = 0; mt < 2; mt++) {
        int r0 = mblk * 128 + m0 + mt * 16 + g;
        int r1 = r0 + 8;
        float* row0 = xi + ((size_t)t * L + r0) * J3P;
        float* row1 = xi + ((size_t)t * L + r1) * J3P;
        #pragma unroll
        for (int nt = 0; nt < 8; nt++) {
            int j0 = nblk * 128 + n0 + nt * 8 + tq * 2;
            if (j0 < J3) {
                float b0 = bi[j0], b1 = bi[j0 + 1];
                float2 v0 = make_float2(acc[mt][nt][0] + b0, acc[mt][nt][1] + b1);
                float2 v1 = make_float2(acc[mt][nt][2] + b0, acc[mt][nt][3] + b1);
                *reinterpret_cast<float2*>(row0 + j0) = v0;
                *reinterpret_cast<float2*>(row1 + j0) = v1;
            }
        }
    }
}

// =====================================================================
// Persistent recurrent MMA kernel, v3b: compact-halo A (NaN fix).
// grid (15 cg, 8 mg) = 120 blocks, 256 thr (8 warps, 4mw x 2nw).
// Per step: stage compact h halo (68 rows x 152ch, hi/lo) ONCE; K-loop
// runs fully from resident smem. A is read by ldmatrix directly from the
// compact buffer: A[l][k] = halo[(l-l0)*304B + 2k]; row stride 304B = 16*19
// -> 8 ldsm rows hit 8 distinct 16B slots mod 128B (conflict-free).
// FIX vs R8: the K-pad region (k>=760) of the last rows reads past the
// 20672 staged bytes into smem that was never written -> NaN*0 = NaN in
// MMA. Zero-init the full halo region (incl. tail) once before the t-loop.
// =====================================================================
#define SM_RB_HI 0
#define SM_RB_LO 49152
#define SM_RA    98304
#define HALO_B   20736          // 68*304 = 20672, rounded up to 128
#define SM_RHH   (SM_RA + 2 * HALO_B)          // 139776
#define SM_REC_TOTAL (SM_RHH + 8192)           // 147968

__global__ __launch_bounds__(256, 1) void rec_mma_kernel(
    const float* __restrict__ xi, float* __restrict__ outp, int layer)
{
    char* sm = reinterpret_cast<char*>(smem);
    const uint32_t smb = smem_u32(sm);
    float* sh_hh = reinterpret_cast<float*>(sm + SM_RHH);
    const int tid = threadIdx.x;
    const int lane = tid & 31, wid = tid >> 5;
    const int cg = blockIdx.x, mg = blockIdx.y;
    const int c0 = cg * 10;
    const int l0 = mg * 64;

    const int mw = wid & 3, nw = wid >> 2;   // 4 x 2 warps
    const int m0w = mw * 16, n0w = nw * 16;

    // A lane offset into compact halo (row stride 304B, k-half select jA)
    const int jA = (lane >> 4) & 1;
    const uint32_t aLane = (uint32_t)(m0w + (lane & 15)) * 304 + jA * 16;
    // B lane addressing (swizzled resident buffer)
    const int bR = n0w + (lane & 7) + ((lane >> 4) & 1) * 8;
    const int bRowOff = bR * 128;
    const int bXor = bR & 7;
    const int jB = (lane >> 3) & 1;

    // ---- zero-init the entire halo region ONCE (covers the K-pad tail that
    //      per-step staging never writes; prevents NaN garbage in MMA) ----
    {
        uint4 z = make_uint4(0, 0, 0, 0);
        for (int u = tid; u < (2 * HALO_B) / 16; u += 256)
            *reinterpret_cast<uint4*>(sm + SM_RA + u * 16) = z;
    }

    // ---- load resident B (weights) once: 2 arr x 12 chunks x 32 rows x 8 segs ----
    for (int u = tid; u < 6144; u += 256) {
        int arr = u / 3072;
        int v = u - arr * 3072;
        int chunk = v >> 8;
        int w = v & 255;
        int row = w >> 3, seg = w & 7;
        const __nv_bfloat16* src =
            (arr ? g_Br_lo : g_Br_hi) + ((size_t)(cg * 32 + row)) * KPAD + chunk * KC + seg * 8;
        uint32_t dst = smb + (arr ? SM_RB_LO : SM_RB_HI)
                     + chunk * 4096 + row * 128 + ((seg ^ (row & 7)) << 4);
        CP_ASYNC16(dst, src);
    }
    CP_COMMIT();
    CP_WAIT0();
    __syncthreads();

    for (int t = 0; t < T; t++) {
        const int cur = t & 1;
        const __nv_bfloat16* hp_hi = g_hp_hi[cur];
        const __nv_bfloat16* hp_lo = g_hp_lo[cur];

        // neighbor sync: wait for mg-1, mg, mg+1 to finish step t-1
        if (t > 0) {
            if (tid < 3) {
                int mgn = mg + tid - 1;
                if (mgn < 0) mgn = 0;
                if (mgn > 7) mgn = 7;
                const unsigned tgt = 15u * (unsigned)t;
                while (g_sync[mgn] < tgt) { }
            }
            __syncthreads();
        }

        // ---- stage compact halo ONCE: flat hp[l0*152 ..], 1292 x 16B per array ----
        {
            const __nv_bfloat16* baseHi = hp_hi + (size_t)l0 * CPAD;
            const __nv_bfloat16* baseLo = hp_lo + (size_t)l0 * CPAD;
            for (int u = tid; u < 2584; u += 256) {
                int arr = u >= 1292;
                int v = arr ? u - 1292 : u;
                const __nv_bfloat16* src = (arr ? baseLo : baseHi) + v * 8;
                uint32_t dst = smb + SM_RA + arr * HALO_B + v * 16;
                CP_ASYNC16(dst, src);
            }
        }
        CP_COMMIT();
        CP_WAIT0();
        __syncthreads();

        float a0[2][4];
        #pragma unroll
        for (int nt = 0; nt < 2; nt++)
            #pragma unroll
            for (int k = 0; k < 4; k++) a0[nt][k] = 0.f;

        const uint32_t aHi = smb + SM_RA + aLane;
        const uint32_t aLo = aHi + HALO_B;

        #pragma unroll 4
        for (int kc = 0; kc < NKC; kc++) {
            const uint32_t bBh = smb + SM_RB_HI + kc * 4096;
            const uint32_t bBl = smb + SM_RB_LO + kc * 4096;
            #pragma unroll
            for (int ks = 0; ks < 4; ks++) {
                uint32_t aoff = kc * 128 + ks * 32;
                uint32_t ah[4], al[4];
                LDSM_X4(ah[0], ah[1], ah[2], ah[3], aHi + aoff);
                LDSM_X4(al[0], al[1], al[2], al[3], aLo + aoff);
                uint32_t boff = bRowOff + (((2 * ks + jB) ^ bXor) << 4);
                uint32_t bh[4], bl[4];
                LDSM_X4(bh[0], bh[1], bh[2], bh[3], bBh + boff);
                LDSM_X4(bl[0], bl[1], bl[2], bl[3], bBl + boff);
                float* d0 = a0[0];
                float* d1 = a0[1];
                MMA16816(d0, ah[0], ah[1], ah[2], ah[3], bh[0], bh[1]);
                MMA16816(d0, al[0], al[1], al[2], al[3], bh[0], bh[1]);
                MMA16816(d0, ah[0], ah[1], ah[2], ah[3], bl[0], bl[1]);
                MMA16816(d1, ah[0], ah[1], ah[2], ah[3], bh[2], bh[3]);
                MMA16816(d1, al[0], al[1], al[2], al[3], bh[2], bh[3]);
                MMA16816(d1, ah[0], ah[1], ah[2], ah[3], bl[2], bl[3]);
            }
        }
        __syncthreads();

        // ---- stage hh into smem ----
        {
            const int g = lane >> 2, tq = lane & 3;
            int r0 = m0w + g;
            int r1 = r0 + 8;
            #pragma unroll
            for (int nt = 0; nt < 2; nt++) {
                int col = n0w + nt * 8 + tq * 2;
                sh_hh[r0 * 32 + col]     = a0[nt][0];
                sh_hh[r0 * 32 + col + 1] = a0[nt][1];
                sh_hh[r1 * 32 + col]     = a0[nt][2];
                sh_hh[r1 * 32 + col + 1] = a0[nt][3];
            }
        }
        __syncthreads();

        // ---- gate epilogue: 64 rows x 10 channels ----
        {
            const float* hfp_cur = g_hfp[cur];
            float* hfp_nxt = g_hfp[cur ^ 1];
            __nv_bfloat16* hpn_hi = g_hp_hi[cur ^ 1];
            __nv_bfloat16* hpn_lo = g_hp_lo[cur ^ 1];
            const float* xit = xi + ((size_t)t * L) * J3P;

            for (int e = tid; e < 640; e += 256) {
                int lr = e / 10, ch = e - lr * 10;
                int l = l0 + lr, c = c0 + ch;
                float hr = sh_hh[lr * 32 + ch];
                float hz = sh_hh[lr * 32 + 10 + ch];
                float hn = sh_hh[lr * 32 + 20 + ch];
                const float* q = xit + (size_t)l * J3P;
                float xr = q[c], xz = q[HID + c], xn = q[2 * HID + c];
                float hp = hfp_cur[l * HID + c];
                float r = sigf(xr + hr);
                float z = sigf(xz + hz);
                float n = tanhfast(xn + r * hn);
                float hnew = n + z * (hp - n);

                hfp_nxt[l * HID + c] = hnew;
                __nv_bfloat16 hi = __float2bfloat16(hnew);
                __nv_bfloat16 lo = __float2bfloat16(hnew - __bfloat162float(hi));
                size_t hpidx = (size_t)(l + 2) * CPAD + c;
                hpn_hi[hpidx] = hi;
                hpn_lo[hpidx] = lo;

                if (layer == 0) {
                    size_t xidx = ((size_t)t * RPAD + (l + 2)) * CPAD + c;
                    g_xtp_hi[xidx] = hi;
                    g_xtp_lo[xidx] = lo;
                } else {
                    outp[((size_t)l * T + t) * HID + c] = hnew;
                }
            }
        }

        // signal completion of step t
        __threadfence();
        __syncthreads();
        if (tid == 0) atomicAdd((unsigned*)&g_sync[mg], 1u);
    }
}

// =====================================================================
extern "C" void kernel_launch(void* const* d_in, const int* in_sizes, int n_in,
                              void* d_out, int out_size)
{
    (void)in_sizes; (void)n_in; (void)out_size;
    const float* xs  = (const float*)d_in[0];
    const float* Wi0 = (const float*)d_in[1];
    const float* bi0 = (const float*)d_in[2];
    const float* Wh0 = (const float*)d_in[3];
    const float* Wi1 = (const float*)d_in[4];
    const float* bi1 = (const float*)d_in[5];
    const float* Wh1 = (const float*)d_in[6];
    float* out = (float*)d_out;

    float* xi;
    cudaGetSymbolAddress((void**)&xi, g_xi);

    const size_t smem_mma = 2 * BUFSZ;
    static int attr_done = 0;
    if (!attr_done) {
        cudaFuncSetAttribute(xi_mma_kernel, cudaFuncAttributeMaxDynamicSharedMemorySize, (int)smem_mma);
        cudaFuncSetAttribute(rec_mma_kernel, cudaFuncAttributeMaxDynamicSharedMemorySize, SM_REC_TOTAL);
        attr_done = 1;
    }

    const size_t n_prep_x = (size_t)T * RPAD * CPAD;
    const int    gx = (int)((n_prep_x + 255) / 256);
    const size_t n_prep_w = (size_t)NB * KPAD;
    const int    gw = (int)((n_prep_w + 255) / 256);
    const size_t n_prep_wr = (size_t)480 * KPAD;
    const int    gwr = (int)((n_prep_wr + 255) / 256);
    const int    gz = (RPAD * CPAD + 255) / 256;
    const dim3 grid_mma(T, 4, 4);
    const dim3 grid_rec(15, 8);

    for (int layer = 0; layer < 2; layer++) {
        const float* Wi = layer ? Wi1 : Wi0;
        const float* bi = layer ? bi1 : bi0;
        const float* Wh = layer ? Wh1 : Wh0;

        if (layer == 0) prep_x_kernel<<<gx, 256>>>(xs);
        prep_w_kernel<<<gw, 256>>>(Wi);
        prep_wrec_kernel<<<gwr, 256>>>(Wh);
        xi_mma_kernel<<<grid_mma, 256, smem_mma>>>(bi, xi);
        zero_rec_kernel<<<gz, 256>>>();
        rec_mma_kernel<<<grid_rec, 256, SM_REC_TOTAL>>>(xi, out, layer);
    }
}

// round 10
// speedup vs baseline: 4.3329x; 1.1582x over previous
#include <cuda_runtime.h>
#include <cuda_bf16.h>
#include <math.h>
#include <stdint.h>

#define L    512
#define T    96
#define CIN  150
#define HID  150
#define J3   450
#define J3P  480
#define KW   5

// padded GEMM geometry (flat sliding-window im2col)
#define CPAD   152            // padded channel stride (150 + 2)
#define KPAD   768            // 5*152 = 760 -> pad to 768 = 12 chunks of 64
#define KC     64
#define NKC    12
#define RPAD   520
#define NB     512            // xi B padded N

// ---------------- scratch ----------------
__device__ float g_xi [(size_t)T * L * J3P];
__device__ volatile unsigned g_sync[8];
// xtp doubles as the h-history for the recurrent pass: slice t holds
// h_t (layer's hidden state after step t) in padded bf16 hi/lo form.
__device__ __align__(256) __nv_bfloat16 g_xtp_hi[(size_t)T * RPAD * CPAD];
__device__ __align__(256) __nv_bfloat16 g_xtp_lo[(size_t)T * RPAD * CPAD];
__device__ __align__(256) __nv_bfloat16 g_B_hi[(size_t)NB * KPAD];
__device__ __align__(256) __nv_bfloat16 g_B_lo[(size_t)NB * KPAD];
__device__ __align__(256) __nv_bfloat16 g_Br_hi[480 * KPAD];
__device__ __align__(256) __nv_bfloat16 g_Br_lo[480 * KPAD];

extern __shared__ float smem[];

// ---------------- PTX helpers (baseline ISA only) ----------------
__device__ __forceinline__ uint32_t smem_u32(const void* p) {
    uint32_t a;
    asm("{ .reg .u64 t; cvta.to.shared.u64 t, %1; cvt.u32.u64 %0, t; }" : "=r"(a) : "l"(p));
    return a;
}
#define CP_ASYNC16(dst, src) \
    asm volatile("cp.async.cg.shared.global [%0], [%1], 16;" :: "r"(dst), "l"(src))
#define CP_ASYNC8(dst, src) \
    asm volatile("cp.async.ca.shared.global [%0], [%1], 8;" :: "r"(dst), "l"(src))
#define CP_COMMIT() asm volatile("cp.async.commit_group;")
#define CP_WAIT1()  asm volatile("cp.async.wait_group 1;")
#define CP_WAIT0()  asm volatile("cp.async.wait_group 0;")
#define LDSM_X4(r0,r1,r2,r3,a) \
    asm volatile("ldmatrix.sync.aligned.m8n8.x4.shared.b16 {%0,%1,%2,%3}, [%4];" \
        : "=r"(r0),"=r"(r1),"=r"(r2),"=r"(r3) : "r"(a))
#define MMA16816(d,a0,a1,a2,a3,b0,b1) \
    asm volatile("mma.sync.aligned.m16n8k16.row.col.f32.bf16.bf16.f32 " \
        "{%0,%1,%2,%3},{%4,%5,%6,%7},{%8,%9},{%0,%1,%2,%3};" \
        : "+f"((d)[0]),"+f"((d)[1]),"+f"((d)[2]),"+f"((d)[3]) \
        : "r"(a0),"r"(a1),"r"(a2),"r"(a3),"r"(b0),"r"(b1))

__device__ __forceinline__ float sigf(float x) {
    float e = __expf(-x);
    return __fdividef(1.f, 1.f + e);
}
__device__ __forceinline__ float tanhfast(float x) {
    return 2.f * sigf(2.f * x) - 1.f;
}

// =====================================================================
// prep kernels
// =====================================================================
__global__ void prep_x_kernel(const float* __restrict__ x) {
    size_t i = (size_t)blockIdx.x * blockDim.x + threadIdx.x;
    const size_t Ntot = (size_t)T * RPAD * CPAD;
    if (i >= Ntot) return;
    int c = i % CPAD;
    int r = (i / CPAD) % RPAD;
    int t = i / ((size_t)CPAD * RPAD);
    float v = 0.f;
    if (r >= 2 && r < 2 + L && c < CIN)
        v = x[(((size_t)(r - 2)) * T + t) * CIN + c];
    __nv_bfloat16 hi = __float2bfloat16(v);
    __nv_bfloat16 lo = __float2bfloat16(v - __bfloat162float(hi));
    g_xtp_hi[i] = hi;
    g_xtp_lo[i] = lo;
}

__global__ void prep_w_kernel(const float* __restrict__ Wi) {
    size_t i = (size_t)blockIdx.x * blockDim.x + threadIdx.x;
    const size_t Ntot = (size_t)NB * KPAD;
    if (i >= Ntot) return;
    int k = i % KPAD;
    int n = i / KPAD;
    int tap = k / CPAD, c = k % CPAD;
    float v = 0.f;
    if (n < J3 && tap < KW && c < CIN)
        v = Wi[((size_t)tap * CIN + c) * J3 + n];
    __nv_bfloat16 hi = __float2bfloat16(v);
    __nv_bfloat16 lo = __float2bfloat16(v - __bfloat162float(hi));
    g_B_hi[i] = hi;
    g_B_lo[i] = lo;
}

// recurrent weights, gate-grouped: row n = cg*32 + j, j<30: gate=j/10, ch=j%10
__global__ void prep_wrec_kernel(const float* __restrict__ Wh) {
    size_t i = (size_t)blockIdx.x * blockDim.x + threadIdx.x;
    const size_t Ntot = (size_t)480 * KPAD;
    if (i >= Ntot) return;
    int k = i % KPAD;
    int n = i / KPAD;
    int cg = n >> 5, j = n & 31;
    int tap = k / CPAD, c = k % CPAD;
    float v = 0.f;
    if (j < 30 && tap < KW && c < CIN) {
        int gate = j / 10, ch = j - gate * 10;
        v = Wh[((size_t)tap * CIN + c) * J3 + gate * HID + cg * 10 + ch];
    }
    __nv_bfloat16 hi = __float2bfloat16(v);
    __nv_bfloat16 lo = __float2bfloat16(v - __bfloat162float(hi));
    g_Br_hi[i] = hi;
    g_Br_lo[i] = lo;
}

__global__ void zero_sync_kernel() {
    if (threadIdx.x < 8) g_sync[threadIdx.x] = 0u;
}

// =====================================================================
// xi via mma.sync bf16 split: grid (96,4,4), 256 thr.
// R10: skip np-tiles that are entirely in the N-padding (cols >= 450).
// =====================================================================
#define BUFSZ 65536

__global__ __launch_bounds__(256, 1) void xi_mma_kernel(
    const float* __restrict__ bi, float* __restrict__ xi)
{
    char* sm = reinterpret_cast<char*>(smem);
    const uint32_t smb = smem_u32(sm);
    const int tid = threadIdx.x;
    const int lane = tid & 31, wid = tid >> 5;
    const int t = blockIdx.x, mblk = blockIdx.y, nblk = blockIdx.z;

    const int mw = wid & 3, nw = wid >> 2;
    const int m0 = mw * 32, n0 = nw * 64;

    int aRow[2], aXor[2];
    const int jA = (lane >> 4) & 1;
    #pragma unroll
    for (int mt = 0; mt < 2; mt++) {
        aRow[mt] = (m0 + mt * 16 + (lane & 15)) * 128;
        aXor[mt] = ((m0 + mt * 16 + (lane & 15)) & 7);
    }
    int bRow[4], bXor[4];
    const int jB = (lane >> 3) & 1;
    #pragma unroll
    for (int np = 0; np < 4; np++) {
        int r = n0 + np * 16 + (lane & 7) + ((lane >> 4) & 1) * 8;
        bRow[np] = r * 128;
        bXor[np] = r & 7;
    }

    const __nv_bfloat16* srcA_hi = g_xtp_hi + ((size_t)t * RPAD + (size_t)mblk * 128) * CPAD;
    const __nv_bfloat16* srcA_lo = g_xtp_lo + ((size_t)t * RPAD + (size_t)mblk * 128) * CPAD;
    const __nv_bfloat16* srcB_hi = g_B_hi + (size_t)nblk * 128 * KPAD;
    const __nv_bfloat16* srcB_lo = g_B_lo + (size_t)nblk * 128 * KPAD;

    float acc[2][8][4];
    #pragma unroll
    for (int mt = 0; mt < 2; mt++)
        #pragma unroll
        for (int nt = 0; nt < 8; nt++)
            #pragma unroll
            for (int k = 0; k < 4; k++) acc[mt][nt][k] = 0.f;

    auto stage = [&](int kc, int buf) {
        const uint32_t base = smb + buf * BUFSZ;
        #pragma unroll
        for (int it = 0; it < 16; it++) {
            int u = it * 256 + tid;
            int arr = u >> 10;
            int v = u & 1023;
            int row = v >> 3, seg = v & 7;
            const __nv_bfloat16* src;
            if (arr == 0)      src = srcA_hi + (size_t)row * CPAD + kc * KC + seg * 8;
            else if (arr == 1) src = srcA_lo + (size_t)row * CPAD + kc * KC + seg * 8;
            else if (arr == 2) src = srcB_hi + (size_t)row * KPAD + kc * KC + seg * 8;
            else               src = srcB_lo + (size_t)row * KPAD + kc * KC + seg * 8;
            uint32_t dst = base + arr * 16384 + row * 128 + ((seg ^ (row & 7)) << 4);
            CP_ASYNC16(dst, src);
        }
    };

    stage(0, 0);
    CP_COMMIT();

    for (int kc = 0; kc < NKC; kc++) {
        const int buf = kc & 1;
        if (kc + 1 < NKC) {
            stage(kc + 1, buf ^ 1);
            CP_COMMIT();
            CP_WAIT1();
        } else {
            CP_WAIT0();
        }
        __syncthreads();

        const uint32_t bA_hi = smb + buf * BUFSZ;
        const uint32_t bA_lo = bA_hi + 16384;
        const uint32_t bB_hi = bA_hi + 32768;
        const uint32_t bB_lo = bA_hi + 49152;

        #pragma unroll
        for (int ks = 0; ks < 4; ks++) {
            uint32_t ah[2][4], al[2][4];
            #pragma unroll
            for (int mt = 0; mt < 2; mt++) {
                uint32_t off = aRow[mt] + (((2 * ks + jA) ^ aXor[mt]) << 4);
                LDSM_X4(ah[mt][0], ah[mt][1], ah[mt][2], ah[mt][3], bA_hi + off);
                LDSM_X4(al[mt][0], al[mt][1], al[mt][2], al[mt][3], bA_lo + off);
            }
            #pragma unroll
            for (int np = 0; np < 4; np++) {
                // skip tiles entirely in the N-padding (never stored; saves ~9% MMAs)
                if (nblk * 128 + n0 + np * 16 >= J3) continue;
                uint32_t off = bRow[np] + (((2 * ks + jB) ^ bXor[np]) << 4);
                uint32_t bh[4], bl[4];
                LDSM_X4(bh[0], bh[1], bh[2], bh[3], bB_hi + off);
                LDSM_X4(bl[0], bl[1], bl[2], bl[3], bB_lo + off);
                #pragma unroll
                for (int mt = 0; mt < 2; mt++) {
                    float* d0 = acc[mt][np * 2];
                    float* d1 = acc[mt][np * 2 + 1];
                    MMA16816(d0, ah[mt][0], ah[mt][1], ah[mt][2], ah[mt][3], bh[0], bh[1]);
                    MMA16816(d0, al[mt][0], al[mt][1], al[mt][2], al[mt][3], bh[0], bh[1]);
                    MMA16816(d0, ah[mt][0], ah[mt][1], ah[mt][2], ah[mt][3], bl[0], bl[1]);
                    MMA16816(d1, ah[mt][0], ah[mt][1], ah[mt][2], ah[mt][3], bh[2], bh[3]);
                    MMA16816(d1, al[mt][0], al[mt][1], al[mt][2], al[mt][3], bh[2], bh[3]);
                    MMA16816(d1, ah[mt][0], ah[mt][1], ah[mt][2], ah[mt][3], bl[2], bl[3]);
                }
            }
        }
        __syncthreads();
    }

    const int g  = lane >> 2;
    const int tq = lane & 3;
    #pragma unroll
    for (int mt = 0; mt < 2; mt++) {
        int r0 = mblk * 128 + m0 + mt * 16 + g;
        int r1 = r0 + 8;
        float* row0 = xi + ((size_t)t * L + r0) * J3P;
        float* row1 = xi + ((size_t)t * L + r1) * J3P;
        #pragma unroll
        for (int nt = 0; nt < 8; nt++) {
            int j0 = nblk * 128 + n0 + nt * 8 + tq * 2;
            if (j0 < J3) {
                float b0 = bi[j0], b1 = bi[j0 + 1];
                float2 v0 = make_float2(acc[mt][nt][0] + b0, acc[mt][nt][1] + b1);
                float2 v1 = make_float2(acc[mt][nt][2] + b0, acc[mt][nt][3] + b1);
                *reinterpret_cast<float2*>(row0 + j0) = v0;
                *reinterpret_cast<float2*>(row1 + j0) = v1;
            }
        }
    }
}

// =====================================================================
// Persistent recurrent MMA kernel, v4:
//  - xtp[t] IS the h-history (no hp ping-pong, no fp32 hfp): halo for
//    step t stages from xtp[t-1]; epilogue writes xtp[t]; h_prev for the
//    z-blend is reconstructed as hi+lo from the staged halo smem.
//  - xi gate-slice prefetched into smem concurrently with the MMA loop
//    (separate cp.async group; wait_group 1 gates only the halo).
//  - t=0: halo already zeroed in smem, no staging at all.
// grid (15 cg, 8 mg) = 120 blocks, 256 thr (8 warps, 4mw x 2nw).
// =====================================================================
#define SM_RB_HI 0
#define SM_RB_LO 49152
#define SM_RA    98304
#define HALO_B   20736          // 68*304 = 20672, rounded up to 128
#define SM_RHH   (SM_RA + 2 * HALO_B)          // 139776
#define SM_XI    (SM_RHH + 8192)               // 147968
#define SM_REC_TOTAL (SM_XI + 8192)            // 156160

__global__ __launch_bounds__(256, 1) void rec_mma_kernel(
    const float* __restrict__ xi, float* __restrict__ outp, int layer)
{
    char* sm = reinterpret_cast<char*>(smem);
    const uint32_t smb = smem_u32(sm);
    float* sh_hh = reinterpret_cast<float*>(sm + SM_RHH);
    float* sh_xi = reinterpret_cast<float*>(sm + SM_XI);
    const int tid = threadIdx.x;
    const int lane = tid & 31, wid = tid >> 5;
    const int cg = blockIdx.x, mg = blockIdx.y;
    const int c0 = cg * 10;
    const int l0 = mg * 64;

    const int mw = wid & 3, nw = wid >> 2;   // 4 x 2 warps
    const int m0w = mw * 16, n0w = nw * 16;

    // A lane offset into compact halo (row stride 304B, k-half select jA)
    const int jA = (lane >> 4) & 1;
    const uint32_t aLane = (uint32_t)(m0w + (lane & 15)) * 304 + jA * 16;
    // B lane addressing (swizzled resident buffer)
    const int bR = n0w + (lane & 7) + ((lane >> 4) & 1) * 8;
    const int bRowOff = bR * 128;
    const int bXor = bR & 7;
    const int jB = (lane >> 3) & 1;

    // ---- zero-init the entire halo region ONCE (t=0 state + K-pad tail) ----
    {
        uint4 z = make_uint4(0, 0, 0, 0);
        for (int u = tid; u < (2 * HALO_B) / 16; u += 256)
            *reinterpret_cast<uint4*>(sm + SM_RA + u * 16) = z;
    }

    // ---- load resident B (weights) once: 2 arr x 12 chunks x 32 rows x 8 segs ----
    for (int u = tid; u < 6144; u += 256) {
        int arr = u / 3072;
        int v = u - arr * 3072;
        int chunk = v >> 8;
        int w = v & 255;
        int row = w >> 3, seg = w & 7;
        const __nv_bfloat16* src =
            (arr ? g_Br_lo : g_Br_hi) + ((size_t)(cg * 32 + row)) * KPAD + chunk * KC + seg * 8;
        uint32_t dst = smb + (arr ? SM_RB_LO : SM_RB_HI)
                     + chunk * 4096 + row * 128 + ((seg ^ (row & 7)) << 4);
        CP_ASYNC16(dst, src);
    }
    CP_COMMIT();
    CP_WAIT0();
    __syncthreads();

    for (int t = 0; t < T; t++) {
        // neighbor sync: wait for mg-1, mg, mg+1 to finish step t-1
        if (t > 0) {
            if (tid < 3) {
                int mgn = mg + tid - 1;
                if (mgn < 0) mgn = 0;
                if (mgn > 7) mgn = 7;
                const unsigned tgt = 15u * (unsigned)t;
                while (g_sync[mgn] < tgt) { }
            }
            __syncthreads();
        }

        // ---- stage compact halo from xtp[t-1] (group 0, gated before MMA) ----
        if (t > 0) {
            const __nv_bfloat16* baseHi = g_xtp_hi + ((size_t)(t - 1) * RPAD + l0) * CPAD;
            const __nv_bfloat16* baseLo = g_xtp_lo + ((size_t)(t - 1) * RPAD + l0) * CPAD;
            for (int u = tid; u < 2584; u += 256) {
                int arr = u >= 1292;
                int v = arr ? u - 1292 : u;
                const __nv_bfloat16* src = (arr ? baseLo : baseHi) + v * 8;
                uint32_t dst = smb + SM_RA + arr * HALO_B + v * 16;
                CP_ASYNC16(dst, src);
            }
            CP_COMMIT();
        }
        // ---- prefetch xi gate slice (group 1, only needed at epilogue) ----
        {
            const float* xibase = xi + ((size_t)t * L + l0) * J3P + c0;
            for (int u = tid; u < 960; u += 256) {
                int lr = u / 15, rem = u - lr * 15;
                int gate = rem / 5, seg = rem - gate * 5;
                const float* src = xibase + (size_t)lr * J3P + gate * HID + seg * 2;
                uint32_t dst = smb + SM_XI + lr * 128 + gate * 40 + seg * 8;
                CP_ASYNC8(dst, src);
            }
            CP_COMMIT();
        }
        if (t > 0) CP_WAIT1();   // halo complete; xi may still be in flight
        __syncthreads();

        float a0[2][4];
        #pragma unroll
        for (int nt = 0; nt < 2; nt++)
            #pragma unroll
            for (int k = 0; k < 4; k++) a0[nt][k] = 0.f;

        const uint32_t aHi = smb + SM_RA + aLane;
        const uint32_t aLo = aHi + HALO_B;

        #pragma unroll 4
        for (int kc = 0; kc < NKC; kc++) {
            const uint32_t bBh = smb + SM_RB_HI + kc * 4096;
            const uint32_t bBl = smb + SM_RB_LO + kc * 4096;
            #pragma unroll
            for (int ks = 0; ks < 4; ks++) {
                uint32_t aoff = kc * 128 + ks * 32;
                uint32_t ah[4], al[4];
                LDSM_X4(ah[0], ah[1], ah[2], ah[3], aHi + aoff);
                LDSM_X4(al[0], al[1], al[2], al[3], aLo + aoff);
                uint32_t boff = bRowOff + (((2 * ks + jB) ^ bXor) << 4);
                uint32_t bh[4], bl[4];
                LDSM_X4(bh[0], bh[1], bh[2], bh[3], bBh + boff);
                LDSM_X4(bl[0], bl[1], bl[2], bl[3], bBl + boff);
                float* d0 = a0[0];
                float* d1 = a0[1];
                MMA16816(d0, ah[0], ah[1], ah[2], ah[3], bh[0], bh[1]);
                MMA16816(d0, al[0], al[1], al[2], al[3], bh[0], bh[1]);
                MMA16816(d0, ah[0], ah[1], ah[2], ah[3], bl[0], bl[1]);
                MMA16816(d1, ah[0], ah[1], ah[2], ah[3], bh[2], bh[3]);
                MMA16816(d1, al[0], al[1], al[2], al[3], bh[2], bh[3]);
                MMA16816(d1, ah[0], ah[1], ah[2], ah[3], bl[2], bl[3]);
            }
        }

        // ---- stage hh into smem ----
        {
            const int g = lane >> 2, tq = lane & 3;
            int r0 = m0w + g;
            int r1 = r0 + 8;
            #pragma unroll
            for (int nt = 0; nt < 2; nt++) {
                int col = n0w + nt * 8 + tq * 2;
                sh_hh[r0 * 32 + col]     = a0[nt][0];
                sh_hh[r0 * 32 + col + 1] = a0[nt][1];
                sh_hh[r1 * 32 + col]     = a0[nt][2];
                sh_hh[r1 * 32 + col + 1] = a0[nt][3];
            }
        }
        CP_WAIT0();       // xi slice now resident
        __syncthreads();

        // ---- gate epilogue: 64 rows x 10 channels, all smem-sourced ----
        {
            for (int e = tid; e < 640; e += 256) {
                int lr = e / 10, ch = e - lr * 10;
                int l = l0 + lr, c = c0 + ch;
                float hr = sh_hh[lr * 32 + ch];
                float hz = sh_hh[lr * 32 + 10 + ch];
                float hn = sh_hh[lr * 32 + 20 + ch];
                const float* qx = sh_xi + lr * 32;
                float xr = qx[ch], xz = qx[10 + ch], xn = qx[20 + ch];
                // h_prev reconstructed from the staged halo (hi+lo)
                uint32_t hoff = (uint32_t)(lr + 2) * 304 + 2u * (uint32_t)c;
                float hpv =
                    __bfloat162float(*reinterpret_cast<__nv_bfloat16*>(sm + SM_RA + hoff)) +
                    __bfloat162float(*reinterpret_cast<__nv_bfloat16*>(sm + SM_RA + HALO_B + hoff));
                float r = sigf(xr + hr);
                float z = sigf(xz + hz);
                float n = tanhfast(xn + r * hn);
                float hnew = n + z * (hpv - n);

                __nv_bfloat16 hi = __float2bfloat16(hnew);
                __nv_bfloat16 lo = __float2bfloat16(hnew - __bfloat162float(hi));
                size_t xidx = ((size_t)t * RPAD + (l + 2)) * CPAD + c;
                g_xtp_hi[xidx] = hi;
                g_xtp_lo[xidx] = lo;
                if (layer == 1)
                    outp[((size_t)l * T + t) * HID + c] = hnew;
            }
        }

        // signal completion of step t
        __threadfence();
        __syncthreads();
        if (tid == 0) atomicAdd((unsigned*)&g_sync[mg], 1u);
    }
}

// =====================================================================
extern "C" void kernel_launch(void* const* d_in, const int* in_sizes, int n_in,
                              void* d_out, int out_size)
{
    (void)in_sizes; (void)n_in; (void)out_size;
    const float* xs  = (const float*)d_in[0];
    const float* Wi0 = (const float*)d_in[1];
    const float* bi0 = (const float*)d_in[2];
    const float* Wh0 = (const float*)d_in[3];
    const float* Wi1 = (const float*)d_in[4];
    const float* bi1 = (const float*)d_in[5];
    const float* Wh1 = (const float*)d_in[6];
    float* out = (float*)d_out;

    float* xi;
    cudaGetSymbolAddress((void**)&xi, g_xi);

    const size_t smem_mma = 2 * BUFSZ;
    static int attr_done = 0;
    if (!attr_done) {
        cudaFuncSetAttribute(xi_mma_kernel, cudaFuncAttributeMaxDynamicSharedMemorySize, (int)smem_mma);
        cudaFuncSetAttribute(rec_mma_kernel, cudaFuncAttributeMaxDynamicSharedMemorySize, SM_REC_TOTAL);
        attr_done = 1;
    }

    const size_t n_prep_x = (size_t)T * RPAD * CPAD;
    const int    gx = (int)((n_prep_x + 255) / 256);
    const size_t n_prep_w = (size_t)NB * KPAD;
    const int    gw = (int)((n_prep_w + 255) / 256);
    const size_t n_prep_wr = (size_t)480 * KPAD;
    const int    gwr = (int)((n_prep_wr + 255) / 256);
    const dim3 grid_mma(T, 4, 4);
    const dim3 grid_rec(15, 8);

    for (int layer = 0; layer < 2; layer++) {
        const float* Wi = layer ? Wi1 : Wi0;
        const float* bi = layer ? bi1 : bi0;
        const float* Wh = layer ? Wh1 : Wh0;

        if (layer == 0) prep_x_kernel<<<gx, 256>>>(xs);
        prep_w_kernel<<<gw, 256>>>(Wi);
        prep_wrec_kernel<<<gwr, 256>>>(Wh);
        xi_mma_kernel<<<grid_mma, 256, smem_mma>>>(bi, xi);
        zero_sync_kernel<<<1, 32>>>();
        rec_mma_kernel<<<grid_rec, 256, SM_REC_TOTAL>>>(xi, out, layer);
    }
}